// round 2
// baseline (speedup 1.0000x reference)
#include <cuda_runtime.h>
#include <math.h>

#define B_  4
#define S_  2048
#define D_  1024
#define R_  512
#define H_  8
#define DH_ 64
#define NC_ 8
#define NE_ 8
#define T_  (B_*S_)   // 8192 tokens

// ---------------- scratch (no allocations allowed) ----------------
__device__ float g_W3[3][T_][NC_];     // q/k/v router weights (softmaxed)
__device__ float g_Q[(size_t)T_*R_];
__device__ float g_K[(size_t)T_*R_];
__device__ float g_V[(size_t)T_*R_];
__device__ float g_AO[(size_t)T_*R_]; // attention output [T, R]
__device__ float g_WO[T_][NE_];       // output router weights

// ================== router q/k/v: logits + softmax ==================
__global__ void router3_kernel(const float* __restrict__ x,
                               const float* __restrict__ wq,
                               const float* __restrict__ wk,
                               const float* __restrict__ wv) {
    __shared__ float xs[D_];
    __shared__ float logits[3][NC_];
    const int t = blockIdx.x;
    const float* xr = x + (size_t)t * D_;
    for (int i = threadIdx.x; i < D_; i += 256) xs[i] = xr[i];
    __syncthreads();
    const int warp = threadIdx.x >> 5, lane = threadIdx.x & 31;  // warp == neuron n
    const float* wr[3] = {wq, wk, wv};
    for (int rt = 0; rt < 3; rt++) {
        const float* w = wr[rt] + warp * D_;
        float s = 0.f;
        for (int d = lane; d < D_; d += 32) s += xs[d] * w[d];
        #pragma unroll
        for (int o = 16; o > 0; o >>= 1) s += __shfl_xor_sync(0xffffffffu, s, o);
        if (lane == 0) logits[rt][warp] = s;
    }
    __syncthreads();
    if (threadIdx.x < 3) {
        const int rt = threadIdx.x;
        float m = -1e30f;
        for (int n = 0; n < NC_; n++) m = fmaxf(m, logits[rt][n]);
        float e[NC_], sum = 0.f;
        for (int n = 0; n < NC_; n++) { e[n] = expf(logits[rt][n] - m); sum += e[n]; }
        const float inv = 1.f / sum;
        for (int n = 0; n < NC_; n++) g_W3[rt][t][n] = e[n] * inv;
    }
}

// ================== fused compress: Q,K,V in one pass ==================
// Q[t,r] = sum_n wq[t,n] * sum_d x[t,d]*CN[n,d,r]  (K,V same partials!)
__global__ __launch_bounds__(256) void compress_kernel(
    const float* __restrict__ x, const float* __restrict__ cn) {
    __shared__ float Xs[16][64];            // [k][token]  (transposed)
    __shared__ float Bs[16][64];            // [k][r]
    __shared__ float Ws[3][NC_][64];        // router weights per local row
    const int c0 = blockIdx.x * 64;         // r tile
    const int t0 = blockIdx.y * 64;         // token tile
    const int tid = threadIdx.x;
    const int ty = tid >> 4, tx = tid & 15;
    for (int idx = tid; idx < 3 * NC_ * 64; idx += 256) {
        const int rt = idx / (NC_ * 64);
        const int n  = (idx >> 6) % NC_;
        const int row = idx & 63;
        Ws[rt][n][row] = g_W3[rt][t0 + row][n];
    }
    float accq[4][4] = {}, acck[4][4] = {}, accv[4][4] = {};
    const int lrowX = tid >> 2, lc4X = tid & 3;     // X loader mapping
    const int lkB   = tid >> 4, lc4B = tid & 15;    // B loader mapping

    for (int n = 0; n < NC_; n++) {
        float part[4][4] = {};
        const float* bn = cn + (size_t)n * D_ * R_;
        for (int d0 = 0; d0 < D_; d0 += 16) {
            __syncthreads();
            const float4 xa = *(const float4*)(x + (size_t)(t0 + lrowX) * D_ + d0 + lc4X * 4);
            Xs[lc4X*4+0][lrowX] = xa.x; Xs[lc4X*4+1][lrowX] = xa.y;
            Xs[lc4X*4+2][lrowX] = xa.z; Xs[lc4X*4+3][lrowX] = xa.w;
            *(float4*)&Bs[lkB][lc4B*4] =
                *(const float4*)(bn + (size_t)(d0 + lkB) * R_ + c0 + lc4B * 4);
            __syncthreads();
            #pragma unroll
            for (int kk = 0; kk < 16; kk++) {
                const float4 a = *(const float4*)&Xs[kk][ty*4];
                const float4 b = *(const float4*)&Bs[kk][tx*4];
                const float av[4] = {a.x, a.y, a.z, a.w};
                const float bv[4] = {b.x, b.y, b.z, b.w};
                #pragma unroll
                for (int i = 0; i < 4; i++)
                    #pragma unroll
                    for (int j = 0; j < 4; j++)
                        part[i][j] += av[i] * bv[j];
            }
        }
        #pragma unroll
        for (int i = 0; i < 4; i++) {
            const float wq = Ws[0][n][ty*4+i];
            const float wk = Ws[1][n][ty*4+i];
            const float wv = Ws[2][n][ty*4+i];
            #pragma unroll
            for (int j = 0; j < 4; j++) {
                accq[i][j] += wq * part[i][j];
                acck[i][j] += wk * part[i][j];
                accv[i][j] += wv * part[i][j];
            }
        }
    }
    #pragma unroll
    for (int i = 0; i < 4; i++) {
        const size_t t = (size_t)(t0 + ty*4 + i);
        #pragma unroll
        for (int j = 0; j < 4; j++) {
            const size_t o = t * R_ + c0 + tx*4 + j;
            g_Q[o] = accq[i][j]; g_K[o] = acck[i][j]; g_V[o] = accv[i][j];
        }
    }
}

// ================== causal flash attention (fp32) ==================
__global__ __launch_bounds__(256) void attn_kernel() {
    __shared__ float Qts[64][64];   // [dh][q]
    __shared__ float KPs[64][64];   // [dh][k], reused as P^T [k][q]
    __shared__ float Vs[64][64];    // [k][dh]
    const int qt = blockIdx.x;
    const int bh = blockIdx.y;
    const int b = bh / H_, h = bh % H_;
    const int tid = threadIdx.x, ty = tid >> 4, tx = tid & 15;
    const size_t base = (size_t)b * S_ * R_ + (size_t)h * DH_;
    const int q0 = qt * 64;

    #pragma unroll
    for (int it = 0; it < 4; it++) {
        const int idx = tid + it * 256;
        const int row = idx >> 4, c4 = idx & 15;
        const float4 v = *(const float4*)(g_Q + base + (size_t)(q0 + row) * R_ + c4 * 4);
        Qts[c4*4+0][row] = v.x; Qts[c4*4+1][row] = v.y;
        Qts[c4*4+2][row] = v.z; Qts[c4*4+3][row] = v.w;
    }
    float m[4], l[4] = {0.f, 0.f, 0.f, 0.f}, acc[4][4] = {};
    #pragma unroll
    for (int i = 0; i < 4; i++) m[i] = -1e30f;

    for (int kt = 0; kt <= qt; kt++) {
        const int k0 = kt * 64;
        __syncthreads();
        #pragma unroll
        for (int it = 0; it < 4; it++) {
            const int idx = tid + it * 256;
            const int row = idx >> 4, c4 = idx & 15;
            const float4 kv = *(const float4*)(g_K + base + (size_t)(k0 + row) * R_ + c4 * 4);
            KPs[c4*4+0][row] = kv.x; KPs[c4*4+1][row] = kv.y;
            KPs[c4*4+2][row] = kv.z; KPs[c4*4+3][row] = kv.w;
            *(float4*)&Vs[row][c4*4] =
                *(const float4*)(g_V + base + (size_t)(k0 + row) * R_ + c4 * 4);
        }
        __syncthreads();
        float s[4][4] = {};
        #pragma unroll 8
        for (int d = 0; d < 64; d++) {
            const float4 qf = *(const float4*)&Qts[d][ty*4];
            const float4 kf = *(const float4*)&KPs[d][tx*4];
            const float qv[4] = {qf.x, qf.y, qf.z, qf.w};
            const float kvv[4] = {kf.x, kf.y, kf.z, kf.w};
            #pragma unroll
            for (int i = 0; i < 4; i++)
                #pragma unroll
                for (int j = 0; j < 4; j++)
                    s[i][j] += qv[i] * kvv[j];
        }
        const float scale = 0.125f;  // 1/sqrt(64)
        const bool diag = (kt == qt);
        float rmax[4];
        #pragma unroll
        for (int i = 0; i < 4; i++) rmax[i] = -1e30f;
        #pragma unroll
        for (int i = 0; i < 4; i++)
            #pragma unroll
            for (int j = 0; j < 4; j++) {
                float v = s[i][j] * scale;
                if (diag && (k0 + tx*4 + j) > (q0 + ty*4 + i)) v = -1e30f;
                s[i][j] = v;
                rmax[i] = fmaxf(rmax[i], v);
            }
        #pragma unroll
        for (int o = 8; o > 0; o >>= 1)
            #pragma unroll
            for (int i = 0; i < 4; i++)
                rmax[i] = fmaxf(rmax[i], __shfl_xor_sync(0xffffffffu, rmax[i], o, 16));
        float mn[4], sc[4], rsum[4] = {};
        #pragma unroll
        for (int i = 0; i < 4; i++) {
            mn[i] = fmaxf(m[i], rmax[i]);
            sc[i] = expf(m[i] - mn[i]);
            m[i] = mn[i];
        }
        #pragma unroll
        for (int i = 0; i < 4; i++)
            #pragma unroll
            for (int j = 0; j < 4; j++) {
                const float p = expf(s[i][j] - mn[i]);
                s[i][j] = p;
                rsum[i] += p;
            }
        #pragma unroll
        for (int o = 8; o > 0; o >>= 1)
            #pragma unroll
            for (int i = 0; i < 4; i++)
                rsum[i] += __shfl_xor_sync(0xffffffffu, rsum[i], o, 16);
        #pragma unroll
        for (int i = 0; i < 4; i++) {
            l[i] = l[i] * sc[i] + rsum[i];
            #pragma unroll
            for (int j = 0; j < 4; j++) acc[i][j] *= sc[i];
        }
        __syncthreads();  // everyone done reading KPs as K^T
        #pragma unroll
        for (int i = 0; i < 4; i++)
            #pragma unroll
            for (int j = 0; j < 4; j++)
                KPs[tx*4+j][ty*4+i] = s[i][j];   // P^T [k][q]
        __syncthreads();
        #pragma unroll 8
        for (int k = 0; k < 64; k++) {
            const float4 pf = *(const float4*)&KPs[k][ty*4];
            const float4 vf = *(const float4*)&Vs[k][tx*4];
            const float pv[4] = {pf.x, pf.y, pf.z, pf.w};
            const float vv[4] = {vf.x, vf.y, vf.z, vf.w};
            #pragma unroll
            for (int i = 0; i < 4; i++)
                #pragma unroll
                for (int j = 0; j < 4; j++)
                    acc[i][j] += pv[i] * vv[j];
        }
    }
    #pragma unroll
    for (int i = 0; i < 4; i++) {
        const float inv = 1.f / l[i];
        const size_t t = (size_t)(b * S_ + q0 + ty*4 + i);
        #pragma unroll
        for (int j = 0; j < 4; j++)
            g_AO[t * R_ + h * DH_ + tx*4 + j] = acc[i][j] * inv;
    }
}

// ================== output router ==================
__global__ void router_o_kernel(const float* __restrict__ wo) {
    __shared__ float as[R_];
    __shared__ float logits[NE_];
    const int t = blockIdx.x;
    for (int i = threadIdx.x; i < R_; i += 256) as[i] = g_AO[(size_t)t * R_ + i];
    __syncthreads();
    const int warp = threadIdx.x >> 5, lane = threadIdx.x & 31;
    const float* w = wo + warp * R_;
    float s = 0.f;
    for (int r = lane; r < R_; r += 32) s += as[r] * w[r];
    #pragma unroll
    for (int o = 16; o > 0; o >>= 1) s += __shfl_xor_sync(0xffffffffu, s, o);
    if (lane == 0) logits[warp] = s;
    __syncthreads();
    if (threadIdx.x == 0) {
        float m = -1e30f;
        for (int n = 0; n < NE_; n++) m = fmaxf(m, logits[n]);
        float e[NE_], sum = 0.f;
        for (int n = 0; n < NE_; n++) { e[n] = expf(logits[n] - m); sum += e[n]; }
        const float inv = 1.f / sum;
        for (int n = 0; n < NE_; n++) g_WO[t][n] = e[n] * inv;
    }
}

// ================== expand ==================
// out[t,d] = sum_n wo[t,n] * sum_r AO[t,r]*EN[n,r,d]
__global__ __launch_bounds__(256) void expand_kernel(
    const float* __restrict__ en, float* __restrict__ out) {
    __shared__ float As[16][64];       // [k][token]
    __shared__ float Bs[16][64];       // [k][d]
    __shared__ float Ws[NE_][64];
    const int c0 = blockIdx.x * 64;    // d tile
    const int t0 = blockIdx.y * 64;    // token tile
    const int tid = threadIdx.x;
    const int ty = tid >> 4, tx = tid & 15;
    for (int idx = tid; idx < NE_ * 64; idx += 256)
        Ws[idx >> 6][idx & 63] = g_WO[t0 + (idx & 63)][idx >> 6];
    float acc[4][4] = {};
    const int lrowA = tid >> 2, lc4A = tid & 3;
    const int lkB   = tid >> 4, lc4B = tid & 15;

    for (int n = 0; n < NE_; n++) {
        float part[4][4] = {};
        const float* bn = en + (size_t)n * R_ * D_;
        for (int r0 = 0; r0 < R_; r0 += 16) {
            __syncthreads();
            const float4 xa = *(const float4*)(g_AO + (size_t)(t0 + lrowA) * R_ + r0 + lc4A * 4);
            As[lc4A*4+0][lrowA] = xa.x; As[lc4A*4+1][lrowA] = xa.y;
            As[lc4A*4+2][lrowA] = xa.z; As[lc4A*4+3][lrowA] = xa.w;
            *(float4*)&Bs[lkB][lc4B*4] =
                *(const float4*)(bn + (size_t)(r0 + lkB) * D_ + c0 + lc4B * 4);
            __syncthreads();
            #pragma unroll
            for (int kk = 0; kk < 16; kk++) {
                const float4 a = *(const float4*)&As[kk][ty*4];
                const float4 b = *(const float4*)&Bs[kk][tx*4];
                const float av[4] = {a.x, a.y, a.z, a.w};
                const float bv[4] = {b.x, b.y, b.z, b.w};
                #pragma unroll
                for (int i = 0; i < 4; i++)
                    #pragma unroll
                    for (int j = 0; j < 4; j++)
                        part[i][j] += av[i] * bv[j];
            }
        }
        #pragma unroll
        for (int i = 0; i < 4; i++) {
            const float w = Ws[n][ty*4+i];
            #pragma unroll
            for (int j = 0; j < 4; j++) acc[i][j] += w * part[i][j];
        }
    }
    #pragma unroll
    for (int i = 0; i < 4; i++) {
        const size_t t = (size_t)(t0 + ty*4 + i);
        #pragma unroll
        for (int j = 0; j < 4; j++)
            out[t * D_ + c0 + tx*4 + j] = acc[i][j];
    }
}

// ================== launch ==================
extern "C" void kernel_launch(void* const* d_in, const int* in_sizes, int n_in,
                              void* d_out, int out_size) {
    const float* x  = (const float*)d_in[0];
    // d_in[1] = mask: deterministic causal tril, handled analytically in attn_kernel
    const float* cn = (const float*)d_in[2];
    const float* en = (const float*)d_in[3];
    const float* wq = (const float*)d_in[4];
    const float* wk = (const float*)d_in[5];
    const float* wv = (const float*)d_in[6];
    const float* wo = (const float*)d_in[7];
    float* out = (float*)d_out;

    router3_kernel<<<T_, 256>>>(x, wq, wk, wv);
    compress_kernel<<<dim3(R_/64, T_/64), 256>>>(x, cn);
    attn_kernel<<<dim3(S_/64, B_*H_), 256>>>();
    router_o_kernel<<<T_, 256>>>(wo);
    expand_kernel<<<dim3(D_/64, T_/64), 256>>>(en, out);
}

// round 8
// speedup vs baseline: 2.5706x; 2.5706x over previous
#include <cuda_runtime.h>
#include <cuda_bf16.h>
#include <math.h>
#include <stdint.h>

#define B_  4
#define S_  2048
#define D_  1024
#define R_  512
#define H_  8
#define DH_ 64
#define NC_ 8
#define NE_ 8
#define T_  (B_*S_)   // 8192 tokens

// ================= helpers =================
__device__ __forceinline__ uint32_t smem_to_u32(const void* p) {
    uint32_t a;
    asm("{ .reg .u64 t; cvta.to.shared.u64 t, %1; cvt.u32.u64 %0, t; }" : "=r"(a) : "l"(p));
    return a;
}
__device__ __forceinline__ void cpa16(uint32_t dst, const void* src) {
    asm volatile("cp.async.cg.shared.global [%0], [%1], 16;" :: "r"(dst), "l"(src));
}
#define CP_COMMIT() asm volatile("cp.async.commit_group;" ::: "memory")
#define CP_WAIT0()  asm volatile("cp.async.wait_group 0;" ::: "memory")
#define CP_WAIT1()  asm volatile("cp.async.wait_group 1;" ::: "memory")

// m16n8k16 bf16 MMA, f32 accum, A row-major, B col-major
__device__ __forceinline__ void mma16816(float* c, const uint32_t* a, const uint32_t* b) {
    asm volatile("mma.sync.aligned.m16n8k16.row.col.f32.bf16.bf16.f32 "
        "{%0,%1,%2,%3}, {%4,%5,%6,%7}, {%8,%9}, {%0,%1,%2,%3};"
        : "+f"(c[0]), "+f"(c[1]), "+f"(c[2]), "+f"(c[3])
        : "r"(a[0]), "r"(a[1]), "r"(a[2]), "r"(a[3]), "r"(b[0]), "r"(b[1]));
}

// ---------------- scratch (no allocations allowed) ----------------
__device__ float g_W3[3][T_][NC_];
__device__ float g_Q[(size_t)T_*R_];
__device__ float g_K[(size_t)T_*R_];
__device__ float g_V[(size_t)T_*R_];
__device__ float g_AO[(size_t)T_*R_];
__device__ float g_WO[T_][NE_];
__device__ __nv_bfloat16 g_Xhi[(size_t)T_*D_],  g_Xlo[(size_t)T_*D_];
__device__ __nv_bfloat16 g_CNThi[(size_t)NC_*R_*D_], g_CNTlo[(size_t)NC_*R_*D_]; // [n][r][d]
__device__ __nv_bfloat16 g_ENThi[(size_t)NE_*D_*R_], g_ENTlo[(size_t)NE_*D_*R_]; // [n][d][r]
__device__ __nv_bfloat16 g_AOhi[(size_t)T_*R_], g_AOlo[(size_t)T_*R_];

// ================= prep: fp32 -> bf16 hi/lo split =================
struct bf4 { __nv_bfloat16 v[4]; };
__global__ void split_bf16_kernel(const float* __restrict__ in,
                                  __nv_bfloat16* __restrict__ oh,
                                  __nv_bfloat16* __restrict__ ol, size_t n4) {
    size_t i = (size_t)blockIdx.x * blockDim.x + threadIdx.x;
    if (i >= n4) return;
    float4 x = ((const float4*)in)[i];
    float xv[4] = {x.x, x.y, x.z, x.w};
    bf4 h, l;
    #pragma unroll
    for (int j = 0; j < 4; j++) {
        h.v[j] = __float2bfloat16(xv[j]);
        l.v[j] = __float2bfloat16(xv[j] - __bfloat162float(h.v[j]));
    }
    ((bf4*)oh)[i] = h;
    ((bf4*)ol)[i] = l;
}

// ===== prep: transpose [n][DIN][DOUT] fp32 -> [n][DOUT][DIN] bf16 hi/lo =====
__global__ void transpose_split_kernel(const float* __restrict__ in,
                                       __nv_bfloat16* __restrict__ oh,
                                       __nv_bfloat16* __restrict__ ol,
                                       int DIN, int DOUT) {
    __shared__ float ts[32][33];
    const int n = blockIdx.z;
    const float* src = in + (size_t)n * DIN * DOUT;
    const int r0 = blockIdx.x * 32, d0 = blockIdx.y * 32;
    for (int k = threadIdx.y; k < 32; k += 8)
        ts[k][threadIdx.x] = src[(size_t)(d0 + k) * DOUT + r0 + threadIdx.x];
    __syncthreads();
    const size_t obase = (size_t)n * DIN * DOUT;
    for (int k = threadIdx.y; k < 32; k += 8) {
        float v = ts[threadIdx.x][k];
        size_t o = obase + (size_t)(r0 + k) * DIN + d0 + threadIdx.x;
        __nv_bfloat16 h = __float2bfloat16(v);
        oh[o] = h;
        ol[o] = __float2bfloat16(v - __bfloat162float(h));
    }
}

// ================== router q/k/v ==================
__global__ void router3_kernel(const float* __restrict__ x,
                               const float* __restrict__ wq,
                               const float* __restrict__ wk,
                               const float* __restrict__ wv) {
    __shared__ float xs[D_];
    __shared__ float logits[3][NC_];
    const int t = blockIdx.x;
    const float* xr = x + (size_t)t * D_;
    for (int i = threadIdx.x; i < D_; i += 256) xs[i] = xr[i];
    __syncthreads();
    const int warp = threadIdx.x >> 5, lane = threadIdx.x & 31;
    const float* wr[3] = {wq, wk, wv};
    for (int rt = 0; rt < 3; rt++) {
        const float* w = wr[rt] + warp * D_;
        float s = 0.f;
        for (int d = lane; d < D_; d += 32) s += xs[d] * w[d];
        #pragma unroll
        for (int o = 16; o > 0; o >>= 1) s += __shfl_xor_sync(0xffffffffu, s, o);
        if (lane == 0) logits[rt][warp] = s;
    }
    __syncthreads();
    if (threadIdx.x < 3) {
        const int rt = threadIdx.x;
        float m = -1e30f;
        for (int n = 0; n < NC_; n++) m = fmaxf(m, logits[rt][n]);
        float e[NC_], sum = 0.f;
        for (int n = 0; n < NC_; n++) { e[n] = expf(logits[rt][n] - m); sum += e[n]; }
        const float inv = 1.f / sum;
        for (int n = 0; n < NC_; n++) g_W3[rt][t][n] = e[n] * inv;
    }
}

// ============== SMEM layout for the mma.sync GEMMs (bytes) ==============
// half-unit row stride 136 (pad 8) -> b32 stride 68 -> conflict-free frag loads
#define LDA_   136
#define OFF_WS   0
#define OFF_AHI  12288
#define OFF_ALO  (OFF_AHI + 128*LDA_*2)            /* 47104 */
#define OFF_B0H  (OFF_ALO + 128*LDA_*2)            /* 81920 */
#define OFF_B0L  (OFF_B0H + 64*LDA_*2)             /* 99328 */
#define OFF_B1H  (OFF_B0L + 64*LDA_*2)             /* 116736 */
#define OFF_B1L  (OFF_B1H + 64*LDA_*2)             /* 134144 */
#define MSMEM_TOTAL (OFF_B1L + 64*LDA_*2)          /* 151552 */

// issue cp.async for an A superchunk (128 rows x 128 halfs, hi+lo)
__device__ __forceinline__ void load_A(uint32_t sb, const __nv_bfloat16* Ahi,
                                       const __nv_bfloat16* Alo, size_t rowstride,
                                       int t0, int kbase, int tid) {
    for (int i = tid; i < 128 * 16; i += 256) {
        const int row = i >> 4, seg = i & 15;
        const uint32_t doff = (uint32_t)(row * LDA_ + seg * 8) * 2;
        const size_t soff = (size_t)(t0 + row) * rowstride + kbase + seg * 8;
        cpa16(sb + OFF_AHI + doff, Ahi + soff);
        cpa16(sb + OFF_ALO + doff, Alo + soff);
    }
}
// issue cp.async for a B tile (64 rows x 128 halfs, hi+lo) into buffer bb
__device__ __forceinline__ void load_B(uint32_t sb, const __nv_bfloat16* Bhi,
                                       const __nv_bfloat16* Blo, size_t rowstride,
                                       size_t rbase, int kbase, int bb, int tid) {
    const uint32_t oh = bb ? OFF_B1H : OFF_B0H;
    const uint32_t ol = bb ? OFF_B1L : OFF_B0L;
    for (int i = tid; i < 64 * 16; i += 256) {
        const int row = i >> 4, seg = i & 15;
        const uint32_t doff = (uint32_t)(row * LDA_ + seg * 8) * 2;
        const size_t soff = (rbase + row) * rowstride + kbase + seg * 8;
        cpa16(sb + oh + doff, Bhi + soff);
        cpa16(sb + ol + doff, Blo + soff);
    }
}

// load A/B fragments + 24 mmas for one k16 step (3-term split)
__device__ __forceinline__ void mma_step(const __nv_bfloat16* Ah, const __nv_bfloat16* Al,
                                         const __nv_bfloat16* Bh, const __nv_bfloat16* Bl,
                                         int wm, int wn, int g, int k04, int kk,
                                         float part[2][4][4]) {
    uint32_t ah[2][4], al[2][4];
    #pragma unroll
    for (int mi = 0; mi < 2; mi++) {
        const int r = wm * 32 + mi * 16 + g;
        ah[mi][0] = *(const uint32_t*)&Ah[r * LDA_ + kk + k04];
        ah[mi][1] = *(const uint32_t*)&Ah[(r + 8) * LDA_ + kk + k04];
        ah[mi][2] = *(const uint32_t*)&Ah[r * LDA_ + kk + k04 + 8];
        ah[mi][3] = *(const uint32_t*)&Ah[(r + 8) * LDA_ + kk + k04 + 8];
        al[mi][0] = *(const uint32_t*)&Al[r * LDA_ + kk + k04];
        al[mi][1] = *(const uint32_t*)&Al[(r + 8) * LDA_ + kk + k04];
        al[mi][2] = *(const uint32_t*)&Al[r * LDA_ + kk + k04 + 8];
        al[mi][3] = *(const uint32_t*)&Al[(r + 8) * LDA_ + kk + k04 + 8];
    }
    uint32_t bh[4][2], bl[4][2];
    #pragma unroll
    for (int nj = 0; nj < 4; nj++) {
        const int rn = wn * 32 + nj * 8 + g;
        bh[nj][0] = *(const uint32_t*)&Bh[rn * LDA_ + kk + k04];
        bh[nj][1] = *(const uint32_t*)&Bh[rn * LDA_ + kk + k04 + 8];
        bl[nj][0] = *(const uint32_t*)&Bl[rn * LDA_ + kk + k04];
        bl[nj][1] = *(const uint32_t*)&Bl[rn * LDA_ + kk + k04 + 8];
    }
    #pragma unroll
    for (int mi = 0; mi < 2; mi++)
        #pragma unroll
        for (int nj = 0; nj < 4; nj++) {
            mma16816(part[mi][nj], ah[mi], bh[nj]);
            mma16816(part[mi][nj], ah[mi], bl[nj]);
            mma16816(part[mi][nj], al[mi], bh[nj]);
        }
}

// ================== compress via mma.sync (split-bf16, 3 terms) ==================
__global__ __launch_bounds__(256, 1) void compress_mma_kernel() {
    extern __shared__ char smem[];
    const uint32_t sb = smem_to_u32(smem);
    const int tid = threadIdx.x, wid = tid >> 5, lane = tid & 31;
    const int wm = wid & 3, wn = wid >> 2;           // 4x2 warp grid
    const int g = lane >> 2, k04 = (lane & 3) * 2;
    const int c0 = blockIdx.x * 64;                  // r tile
    const int t0 = blockIdx.y * 128;                 // token tile

    // router weights: Ws[rt][n][row]
    float* wsf = (float*)(smem + OFF_WS);
    for (int i = tid; i < 3 * NC_ * 128; i += 256) {
        const int rt = i >> 10, n = (i >> 7) & 7, row = i & 127;
        wsf[i] = g_W3[rt][t0 + row][n];
    }

    const int NIT = 8 * NC_;  // 8 superchunks x 8 neurons
    // prologue: G0 = A(sc0)+B(0), G1 = B(1)
    load_A(sb, g_Xhi, g_Xlo, D_, t0, 0, tid);
    load_B(sb, g_CNThi, g_CNTlo, D_, (size_t)0 * R_ + c0, 0, 0, tid);
    CP_COMMIT();
    load_B(sb, g_CNThi, g_CNTlo, D_, (size_t)1 * R_ + c0, 0, 1, tid);
    CP_COMMIT();

    float qa[2][4][4] = {}, ka[2][4][4] = {}, va[2][4][4] = {};
    const __nv_bfloat16* Ah = (const __nv_bfloat16*)(smem + OFF_AHI);
    const __nv_bfloat16* Al = (const __nv_bfloat16*)(smem + OFF_ALO);

    for (int it = 0; it < NIT; it++) {
        const int sc = it >> 3, n = it & 7, bb = it & 1;
        if (it != 0 && (it & 7) == 0) { CP_WAIT0(); } else { CP_WAIT1(); }
        __syncthreads();

        const __nv_bfloat16* Bh = (const __nv_bfloat16*)(smem + (bb ? OFF_B1H : OFF_B0H));
        const __nv_bfloat16* Bl = (const __nv_bfloat16*)(smem + (bb ? OFF_B1L : OFF_B0L));
        float part[2][4][4] = {};
        #pragma unroll
        for (int ks = 0; ks < 8; ks++)
            mma_step(Ah, Al, Bh, Bl, wm, wn, g, k04, ks * 16, part);

        // fold router weights (per superchunk per neuron — linearity)
        #pragma unroll
        for (int mi = 0; mi < 2; mi++) {
            const int r0 = wm * 32 + mi * 16 + g;
            const float wq0 = wsf[0 * 1024 + n * 128 + r0], wq1 = wsf[0 * 1024 + n * 128 + r0 + 8];
            const float wk0 = wsf[1 * 1024 + n * 128 + r0], wk1 = wsf[1 * 1024 + n * 128 + r0 + 8];
            const float wv0 = wsf[2 * 1024 + n * 128 + r0], wv1 = wsf[2 * 1024 + n * 128 + r0 + 8];
            #pragma unroll
            for (int nj = 0; nj < 4; nj++) {
                qa[mi][nj][0] += wq0 * part[mi][nj][0]; qa[mi][nj][1] += wq0 * part[mi][nj][1];
                qa[mi][nj][2] += wq1 * part[mi][nj][2]; qa[mi][nj][3] += wq1 * part[mi][nj][3];
                ka[mi][nj][0] += wk0 * part[mi][nj][0]; ka[mi][nj][1] += wk0 * part[mi][nj][1];
                ka[mi][nj][2] += wk1 * part[mi][nj][2]; ka[mi][nj][3] += wk1 * part[mi][nj][3];
                va[mi][nj][0] += wv0 * part[mi][nj][0]; va[mi][nj][1] += wv0 * part[mi][nj][1];
                va[mi][nj][2] += wv1 * part[mi][nj][2]; va[mi][nj][3] += wv1 * part[mi][nj][3];
            }
        }
        __syncthreads();

        if (it + 1 < NIT) {
            if (((it + 1) & 7) == 0)
                load_A(sb, g_Xhi, g_Xlo, D_, t0, (sc + 1) * 128, tid);
            if (it + 2 < NIT) {
                const int sc2 = (it + 2) >> 3, n2 = (it + 2) & 7;
                load_B(sb, g_CNThi, g_CNTlo, D_, (size_t)n2 * R_ + c0, sc2 * 128, (it + 2) & 1, tid);
            }
            CP_COMMIT();
        }
    }

    // epilogue
    #pragma unroll
    for (int mi = 0; mi < 2; mi++) {
        const int r0 = t0 + wm * 32 + mi * 16 + g;
        #pragma unroll
        for (int nj = 0; nj < 4; nj++) {
            const int cc = c0 + wn * 32 + nj * 8 + k04;
            *(float2*)&g_Q[(size_t)r0 * R_ + cc]       = make_float2(qa[mi][nj][0], qa[mi][nj][1]);
            *(float2*)&g_Q[(size_t)(r0 + 8) * R_ + cc] = make_float2(qa[mi][nj][2], qa[mi][nj][3]);
            *(float2*)&g_K[(size_t)r0 * R_ + cc]       = make_float2(ka[mi][nj][0], ka[mi][nj][1]);
            *(float2*)&g_K[(size_t)(r0 + 8) * R_ + cc] = make_float2(ka[mi][nj][2], ka[mi][nj][3]);
            *(float2*)&g_V[(size_t)r0 * R_ + cc]       = make_float2(va[mi][nj][0], va[mi][nj][1]);
            *(float2*)&g_V[(size_t)(r0 + 8) * R_ + cc] = make_float2(va[mi][nj][2], va[mi][nj][3]);
        }
    }
}

// ================== expand via mma.sync ==================
__global__ __launch_bounds__(256, 1) void expand_mma_kernel(float* __restrict__ out) {
    extern __shared__ char smem[];
    const uint32_t sb = smem_to_u32(smem);
    const int tid = threadIdx.x, wid = tid >> 5, lane = tid & 31;
    const int wm = wid & 3, wn = wid >> 2;
    const int g = lane >> 2, k04 = (lane & 3) * 2;
    const int c0 = blockIdx.x * 64;                  // d tile
    const int t0 = blockIdx.y * 128;                 // token tile

    float* wsf = (float*)(smem + OFF_WS);            // Ws[n][row]
    for (int i = tid; i < NE_ * 128; i += 256) {
        const int n = i >> 7, row = i & 127;
        wsf[i] = g_WO[t0 + row][n];
    }

    const int NIT = 4 * NE_;  // 4 superchunks (K=512) x 8 neurons
    load_A(sb, g_AOhi, g_AOlo, R_, t0, 0, tid);
    load_B(sb, g_ENThi, g_ENTlo, R_, (size_t)0 * D_ + c0, 0, 0, tid);
    CP_COMMIT();
    load_B(sb, g_ENThi, g_ENTlo, R_, (size_t)1 * D_ + c0, 0, 1, tid);
    CP_COMMIT();

    float oa[2][4][4] = {};
    const __nv_bfloat16* Ah = (const __nv_bfloat16*)(smem + OFF_AHI);
    const __nv_bfloat16* Al = (const __nv_bfloat16*)(smem + OFF_ALO);

    for (int it = 0; it < NIT; it++) {
        const int sc = it >> 3, n = it & 7, bb = it & 1;
        if (it != 0 && (it & 7) == 0) { CP_WAIT0(); } else { CP_WAIT1(); }
        __syncthreads();

        const __nv_bfloat16* Bh = (const __nv_bfloat16*)(smem + (bb ? OFF_B1H : OFF_B0H));
        const __nv_bfloat16* Bl = (const __nv_bfloat16*)(smem + (bb ? OFF_B1L : OFF_B0L));
        float part[2][4][4] = {};
        #pragma unroll
        for (int ks = 0; ks < 8; ks++)
            mma_step(Ah, Al, Bh, Bl, wm, wn, g, k04, ks * 16, part);

        #pragma unroll
        for (int mi = 0; mi < 2; mi++) {
            const int r0 = wm * 32 + mi * 16 + g;
            const float w0 = wsf[n * 128 + r0], w1 = wsf[n * 128 + r0 + 8];
            #pragma unroll
            for (int nj = 0; nj < 4; nj++) {
                oa[mi][nj][0] += w0 * part[mi][nj][0]; oa[mi][nj][1] += w0 * part[mi][nj][1];
                oa[mi][nj][2] += w1 * part[mi][nj][2]; oa[mi][nj][3] += w1 * part[mi][nj][3];
            }
        }
        __syncthreads();

        if (it + 1 < NIT) {
            if (((it + 1) & 7) == 0)
                load_A(sb, g_AOhi, g_AOlo, R_, t0, (sc + 1) * 128, tid);
            if (it + 2 < NIT) {
                const int sc2 = (it + 2) >> 3, n2 = (it + 2) & 7;
                load_B(sb, g_ENThi, g_ENTlo, R_, (size_t)n2 * D_ + c0, sc2 * 128, (it + 2) & 1, tid);
            }
            CP_COMMIT();
        }
    }

    #pragma unroll
    for (int mi = 0; mi < 2; mi++) {
        const int r0 = t0 + wm * 32 + mi * 16 + g;
        #pragma unroll
        for (int nj = 0; nj < 4; nj++) {
            const int cc = c0 + wn * 32 + nj * 8 + k04;
            *(float2*)&out[(size_t)r0 * D_ + cc]       = make_float2(oa[mi][nj][0], oa[mi][nj][1]);
            *(float2*)&out[(size_t)(r0 + 8) * D_ + cc] = make_float2(oa[mi][nj][2], oa[mi][nj][3]);
        }
    }
}

// ================== causal flash attention (fp32 SIMT, known-good) ==================
__global__ __launch_bounds__(256) void attn_kernel() {
    __shared__ float Qts[64][64];
    __shared__ float KPs[64][64];
    __shared__ float Vs[64][64];
    const int qt = blockIdx.x;
    const int bh = blockIdx.y;
    const int b = bh / H_, h = bh % H_;
    const int tid = threadIdx.x, ty = tid >> 4, tx = tid & 15;
    const size_t base = (size_t)b * S_ * R_ + (size_t)h * DH_;
    const int q0 = qt * 64;

    #pragma unroll
    for (int it = 0; it < 4; it++) {
        const int idx = tid + it * 256;
        const int row = idx >> 4, c4 = idx & 15;
        const float4 v = *(const float4*)(g_Q + base + (size_t)(q0 + row) * R_ + c4 * 4);
        Qts[c4*4+0][row] = v.x; Qts[c4*4+1][row] = v.y;
        Qts[c4*4+2][row] = v.z; Qts[c4*4+3][row] = v.w;
    }
    float m[4], l[4] = {0.f, 0.f, 0.f, 0.f}, acc[4][4] = {};
    #pragma unroll
    for (int i = 0; i < 4; i++) m[i] = -1e30f;

    for (int kt = 0; kt <= qt; kt++) {
        const int k0 = kt * 64;
        __syncthreads();
        #pragma unroll
        for (int it = 0; it < 4; it++) {
            const int idx = tid + it * 256;
            const int row = idx >> 4, c4 = idx & 15;
            const float4 kv = *(const float4*)(g_K + base + (size_t)(k0 + row) * R_ + c4 * 4);
            KPs[c4*4+0][row] = kv.x; KPs[c4*4+1][row] = kv.y;
            KPs[c4*4+2][row] = kv.z; KPs[c4*4+3][row] = kv.w;
            *(float4*)&Vs[row][c4*4] =
                *(const float4*)(g_V + base + (size_t)(k0 + row) * R_ + c4 * 4);
        }
        __syncthreads();
        float s[4][4] = {};
        #pragma unroll 8
        for (int d = 0; d < 64; d++) {
            const float4 qf = *(const float4*)&Qts[d][ty*4];
            const float4 kf = *(const float4*)&KPs[d][tx*4];
            const float qv[4] = {qf.x, qf.y, qf.z, qf.w};
            const float kvv[4] = {kf.x, kf.y, kf.z, kf.w};
            #pragma unroll
            for (int i = 0; i < 4; i++)
                #pragma unroll
                for (int j = 0; j < 4; j++)
                    s[i][j] += qv[i] * kvv[j];
        }
        const float scale = 0.125f;
        const bool diag = (kt == qt);
        float rmax[4];
        #pragma unroll
        for (int i = 0; i < 4; i++) rmax[i] = -1e30f;
        #pragma unroll
        for (int i = 0; i < 4; i++)
            #pragma unroll
            for (int j = 0; j < 4; j++) {
                float v = s[i][j] * scale;
                if (diag && (k0 + tx*4 + j) > (q0 + ty*4 + i)) v = -1e30f;
                s[i][j] = v;
                rmax[i] = fmaxf(rmax[i], v);
            }
        #pragma unroll
        for (int o = 8; o > 0; o >>= 1)
            #pragma unroll
            for (int i = 0; i < 4; i++)
                rmax[i] = fmaxf(rmax[i], __shfl_xor_sync(0xffffffffu, rmax[i], o, 16));
        float mn[4], sc[4], rsum[4] = {};
        #pragma unroll
        for (int i = 0; i < 4; i++) {
            mn[i] = fmaxf(m[i], rmax[i]);
            sc[i] = expf(m[i] - mn[i]);
            m[i] = mn[i];
        }
        #pragma unroll
        for (int i = 0; i < 4; i++)
            #pragma unroll
            for (int j = 0; j < 4; j++) {
                const float p = expf(s[i][j] - mn[i]);
                s[i][j] = p;
                rsum[i] += p;
            }
        #pragma unroll
        for (int o = 8; o > 0; o >>= 1)
            #pragma unroll
            for (int i = 0; i < 4; i++)
                rsum[i] += __shfl_xor_sync(0xffffffffu, rsum[i], o, 16);
        #pragma unroll
        for (int i = 0; i < 4; i++) {
            l[i] = l[i] * sc[i] + rsum[i];
            #pragma unroll
            for (int j = 0; j < 4; j++) acc[i][j] *= sc[i];
        }
        __syncthreads();
        #pragma unroll
        for (int i = 0; i < 4; i++)
            #pragma unroll
            for (int j = 0; j < 4; j++)
                KPs[tx*4+j][ty*4+i] = s[i][j];
        __syncthreads();
        #pragma unroll 8
        for (int k = 0; k < 64; k++) {
            const float4 pf = *(const float4*)&KPs[k][ty*4];
            const float4 vf = *(const float4*)&Vs[k][tx*4];
            const float pv[4] = {pf.x, pf.y, pf.z, pf.w};
            const float vv[4] = {vf.x, vf.y, vf.z, vf.w};
            #pragma unroll
            for (int i = 0; i < 4; i++)
                #pragma unroll
                for (int j = 0; j < 4; j++)
                    acc[i][j] += pv[i] * vv[j];
        }
    }
    #pragma unroll
    for (int i = 0; i < 4; i++) {
        const float inv = 1.f / l[i];
        const size_t t = (size_t)(b * S_ + q0 + ty*4 + i);
        #pragma unroll
        for (int j = 0; j < 4; j++)
            g_AO[t * R_ + h * DH_ + tx*4 + j] = acc[i][j] * inv;
    }
}

// ================== output router ==================
__global__ void router_o_kernel(const float* __restrict__ wo) {
    __shared__ float as[R_];
    __shared__ float logits[NE_];
    const int t = blockIdx.x;
    for (int i = threadIdx.x; i < R_; i += 256) as[i] = g_AO[(size_t)t * R_ + i];
    __syncthreads();
    const int warp = threadIdx.x >> 5, lane = threadIdx.x & 31;
    const float* w = wo + warp * R_;
    float s = 0.f;
    for (int r = lane; r < R_; r += 32) s += as[r] * w[r];
    #pragma unroll
    for (int o = 16; o > 0; o >>= 1) s += __shfl_xor_sync(0xffffffffu, s, o);
    if (lane == 0) logits[warp] = s;
    __syncthreads();
    if (threadIdx.x == 0) {
        float m = -1e30f;
        for (int n = 0; n < NE_; n++) m = fmaxf(m, logits[n]);
        float e[NE_], sum = 0.f;
        for (int n = 0; n < NE_; n++) { e[n] = expf(logits[n] - m); sum += e[n]; }
        const float inv = 1.f / sum;
        for (int n = 0; n < NE_; n++) g_WO[t][n] = e[n] * inv;
    }
}

__global__ void split_ao_kernel(size_t n4) {
    size_t i = (size_t)blockIdx.x * blockDim.x + threadIdx.x;
    if (i >= n4) return;
    float4 x = ((const float4*)g_AO)[i];
    float xv[4] = {x.x, x.y, x.z, x.w};
    bf4 h, l;
    #pragma unroll
    for (int j = 0; j < 4; j++) {
        h.v[j] = __float2bfloat16(xv[j]);
        l.v[j] = __float2bfloat16(xv[j] - __bfloat162float(h.v[j]));
    }
    ((bf4*)g_AOhi)[i] = h;
    ((bf4*)g_AOlo)[i] = l;
}

// ================== launch ==================
extern "C" void kernel_launch(void* const* d_in, const int* in_sizes, int n_in,
                              void* d_out, int out_size) {
    const float* x  = (const float*)d_in[0];
    const float* cn = (const float*)d_in[2];
    const float* en = (const float*)d_in[3];
    const float* wq = (const float*)d_in[4];
    const float* wk = (const float*)d_in[5];
    const float* wv = (const float*)d_in[6];
    const float* wo = (const float*)d_in[7];
    float* out = (float*)d_out;

    cudaFuncSetAttribute((const void*)compress_mma_kernel,
                         cudaFuncAttributeMaxDynamicSharedMemorySize, MSMEM_TOTAL);
    cudaFuncSetAttribute((const void*)expand_mma_kernel,
                         cudaFuncAttributeMaxDynamicSharedMemorySize, MSMEM_TOTAL);

    __nv_bfloat16 *xhi, *xlo, *cnthi, *cntlo, *enthi, *entlo;
    cudaGetSymbolAddress((void**)&xhi, g_Xhi);
    cudaGetSymbolAddress((void**)&xlo, g_Xlo);
    cudaGetSymbolAddress((void**)&cnthi, g_CNThi);
    cudaGetSymbolAddress((void**)&cntlo, g_CNTlo);
    cudaGetSymbolAddress((void**)&enthi, g_ENThi);
    cudaGetSymbolAddress((void**)&entlo, g_ENTlo);

    // prep
    split_bf16_kernel<<<(unsigned)((size_t)T_*D_/4/256), 256>>>(x, xhi, xlo, (size_t)T_*D_/4);
    transpose_split_kernel<<<dim3(R_/32, D_/32, NC_), dim3(32, 8)>>>(cn, cnthi, cntlo, D_, R_);
    transpose_split_kernel<<<dim3(D_/32, R_/32, NE_), dim3(32, 8)>>>(en, enthi, entlo, R_, D_);
    router3_kernel<<<T_, 256>>>(x, wq, wk, wv);
    // main pipeline
    compress_mma_kernel<<<dim3(R_/64, T_/128), 256, MSMEM_TOTAL>>>();
    attn_kernel<<<dim3(S_/64, B_*H_), 256>>>();
    router_o_kernel<<<T_, 256>>>(wo);
    split_ao_kernel<<<(unsigned)((size_t)T_*R_/4/256), 256>>>((size_t)T_*R_/4);
    expand_mma_kernel<<<dim3(D_/64, T_/128), 256, MSMEM_TOTAL>>>(out);
}

// round 13
// speedup vs baseline: 3.5481x; 1.3803x over previous
#include <cuda_runtime.h>
#include <cuda_bf16.h>
#include <math.h>
#include <stdint.h>

#define B_  4
#define S_  2048
#define D_  1024
#define R_  512
#define H_  8
#define DH_ 64
#define NC_ 8
#define NE_ 8
#define T_  (B_*S_)   // 8192 tokens

// ================= helpers =================
__device__ __forceinline__ uint32_t smem_to_u32(const void* p) {
    uint32_t a;
    asm("{ .reg .u64 t; cvta.to.shared.u64 t, %1; cvt.u32.u64 %0, t; }" : "=r"(a) : "l"(p));
    return a;
}
__device__ __forceinline__ void cpa16(uint32_t dst, const void* src) {
    asm volatile("cp.async.cg.shared.global [%0], [%1], 16;" :: "r"(dst), "l"(src));
}
#define CP_COMMIT() asm volatile("cp.async.commit_group;" ::: "memory")
#define CP_WAIT0()  asm volatile("cp.async.wait_group 0;" ::: "memory")
#define CP_WAIT1()  asm volatile("cp.async.wait_group 1;" ::: "memory")

// m16n8k16 bf16 MMA, f32 accum, A row-major, B col-major
__device__ __forceinline__ void mma16816(float* c, const uint32_t* a, const uint32_t* b) {
    asm volatile("mma.sync.aligned.m16n8k16.row.col.f32.bf16.bf16.f32 "
        "{%0,%1,%2,%3}, {%4,%5,%6,%7}, {%8,%9}, {%0,%1,%2,%3};"
        : "+f"(c[0]), "+f"(c[1]), "+f"(c[2]), "+f"(c[3])
        : "r"(a[0]), "r"(a[1]), "r"(a[2]), "r"(a[3]), "r"(b[0]), "r"(b[1]));
}
// pack two floats into bf16x2 hi + residual lo
__device__ __forceinline__ void pack_hilo(float x, float y, uint32_t& hi, uint32_t& lo) {
    __nv_bfloat16 hx = __float2bfloat16(x), hy = __float2bfloat16(y);
    __nv_bfloat162 hv; hv.x = hx; hv.y = hy;
    hi = *(uint32_t*)&hv;
    __nv_bfloat162 lv;
    lv.x = __float2bfloat16(x - __bfloat162float(hx));
    lv.y = __float2bfloat16(y - __bfloat162float(hy));
    lo = *(uint32_t*)&lv;
}

// ---------------- scratch (no allocations allowed) ----------------
__device__ float g_W3[3][T_][NC_];
__device__ float g_Q[(size_t)T_*R_];
__device__ float g_K[(size_t)T_*R_];
__device__ float g_V[(size_t)T_*R_];
__device__ float g_AO[(size_t)T_*R_];
__device__ float g_WO[T_][NE_];
__device__ __nv_bfloat16 g_Xhi[(size_t)T_*D_],  g_Xlo[(size_t)T_*D_];
__device__ __nv_bfloat16 g_CNThi[(size_t)NC_*R_*D_], g_CNTlo[(size_t)NC_*R_*D_]; // [n][r][d]
__device__ __nv_bfloat16 g_ENThi[(size_t)NE_*D_*R_], g_ENTlo[(size_t)NE_*D_*R_]; // [n][d][r]
__device__ __nv_bfloat16 g_AOhi[(size_t)T_*R_], g_AOlo[(size_t)T_*R_];

// ================= prep: fp32 -> bf16 hi/lo split =================
struct bf4 { __nv_bfloat16 v[4]; };
__global__ void split_bf16_kernel(const float* __restrict__ in,
                                  __nv_bfloat16* __restrict__ oh,
                                  __nv_bfloat16* __restrict__ ol, size_t n4) {
    size_t i = (size_t)blockIdx.x * blockDim.x + threadIdx.x;
    if (i >= n4) return;
    float4 x = ((const float4*)in)[i];
    float xv[4] = {x.x, x.y, x.z, x.w};
    bf4 h, l;
    #pragma unroll
    for (int j = 0; j < 4; j++) {
        h.v[j] = __float2bfloat16(xv[j]);
        l.v[j] = __float2bfloat16(xv[j] - __bfloat162float(h.v[j]));
    }
    ((bf4*)oh)[i] = h;
    ((bf4*)ol)[i] = l;
}

// ===== prep: transpose [n][DIN][DOUT] fp32 -> [n][DOUT][DIN] bf16 hi/lo =====
__global__ void transpose_split_kernel(const float* __restrict__ in,
                                       __nv_bfloat16* __restrict__ oh,
                                       __nv_bfloat16* __restrict__ ol,
                                       int DIN, int DOUT) {
    __shared__ float ts[32][33];
    const int n = blockIdx.z;
    const float* src = in + (size_t)n * DIN * DOUT;
    const int r0 = blockIdx.x * 32, d0 = blockIdx.y * 32;
    for (int k = threadIdx.y; k < 32; k += 8)
        ts[k][threadIdx.x] = src[(size_t)(d0 + k) * DOUT + r0 + threadIdx.x];
    __syncthreads();
    const size_t obase = (size_t)n * DIN * DOUT;
    for (int k = threadIdx.y; k < 32; k += 8) {
        float v = ts[threadIdx.x][k];
        size_t o = obase + (size_t)(r0 + k) * DIN + d0 + threadIdx.x;
        __nv_bfloat16 h = __float2bfloat16(v);
        oh[o] = h;
        ol[o] = __float2bfloat16(v - __bfloat162float(h));
    }
}

// ================== router q/k/v ==================
__global__ void router3_kernel(const float* __restrict__ x,
                               const float* __restrict__ wq,
                               const float* __restrict__ wk,
                               const float* __restrict__ wv) {
    __shared__ float xs[D_];
    __shared__ float logits[3][NC_];
    const int t = blockIdx.x;
    const float* xr = x + (size_t)t * D_;
    for (int i = threadIdx.x; i < D_; i += 256) xs[i] = xr[i];
    __syncthreads();
    const int warp = threadIdx.x >> 5, lane = threadIdx.x & 31;
    const float* wr[3] = {wq, wk, wv};
    for (int rt = 0; rt < 3; rt++) {
        const float* w = wr[rt] + warp * D_;
        float s = 0.f;
        for (int d = lane; d < D_; d += 32) s += xs[d] * w[d];
        #pragma unroll
        for (int o = 16; o > 0; o >>= 1) s += __shfl_xor_sync(0xffffffffu, s, o);
        if (lane == 0) logits[rt][warp] = s;
    }
    __syncthreads();
    if (threadIdx.x < 3) {
        const int rt = threadIdx.x;
        float m = -1e30f;
        for (int n = 0; n < NC_; n++) m = fmaxf(m, logits[rt][n]);
        float e[NC_], sum = 0.f;
        for (int n = 0; n < NC_; n++) { e[n] = expf(logits[rt][n] - m); sum += e[n]; }
        const float inv = 1.f / sum;
        for (int n = 0; n < NC_; n++) g_W3[rt][t][n] = e[n] * inv;
    }
}

// ============== SMEM layout for the mma.sync GEMMs (bytes) ==============
#define LDA_   136
#define OFF_WS   0
#define OFF_AHI  12288
#define OFF_ALO  (OFF_AHI + 128*LDA_*2)
#define OFF_B0H  (OFF_ALO + 128*LDA_*2)
#define OFF_B0L  (OFF_B0H + 64*LDA_*2)
#define OFF_B1H  (OFF_B0L + 64*LDA_*2)
#define OFF_B1L  (OFF_B1H + 64*LDA_*2)
#define MSMEM_TOTAL (OFF_B1L + 64*LDA_*2)

__device__ __forceinline__ void load_A(uint32_t sb, const __nv_bfloat16* Ahi,
                                       const __nv_bfloat16* Alo, size_t rowstride,
                                       int t0, int kbase, int tid) {
    for (int i = tid; i < 128 * 16; i += 256) {
        const int row = i >> 4, seg = i & 15;
        const uint32_t doff = (uint32_t)(row * LDA_ + seg * 8) * 2;
        const size_t soff = (size_t)(t0 + row) * rowstride + kbase + seg * 8;
        cpa16(sb + OFF_AHI + doff, Ahi + soff);
        cpa16(sb + OFF_ALO + doff, Alo + soff);
    }
}
__device__ __forceinline__ void load_B(uint32_t sb, const __nv_bfloat16* Bhi,
                                       const __nv_bfloat16* Blo, size_t rowstride,
                                       size_t rbase, int kbase, int bb, int tid) {
    const uint32_t oh = bb ? OFF_B1H : OFF_B0H;
    const uint32_t ol = bb ? OFF_B1L : OFF_B0L;
    for (int i = tid; i < 64 * 16; i += 256) {
        const int row = i >> 4, seg = i & 15;
        const uint32_t doff = (uint32_t)(row * LDA_ + seg * 8) * 2;
        const size_t soff = (rbase + row) * rowstride + kbase + seg * 8;
        cpa16(sb + oh + doff, Bhi + soff);
        cpa16(sb + ol + doff, Blo + soff);
    }
}

__device__ __forceinline__ void mma_step(const __nv_bfloat16* Ah, const __nv_bfloat16* Al,
                                         const __nv_bfloat16* Bh, const __nv_bfloat16* Bl,
                                         int wm, int wn, int g, int k04, int kk,
                                         float part[2][4][4]) {
    uint32_t ah[2][4], al[2][4];
    #pragma unroll
    for (int mi = 0; mi < 2; mi++) {
        const int r = wm * 32 + mi * 16 + g;
        ah[mi][0] = *(const uint32_t*)&Ah[r * LDA_ + kk + k04];
        ah[mi][1] = *(const uint32_t*)&Ah[(r + 8) * LDA_ + kk + k04];
        ah[mi][2] = *(const uint32_t*)&Ah[r * LDA_ + kk + k04 + 8];
        ah[mi][3] = *(const uint32_t*)&Ah[(r + 8) * LDA_ + kk + k04 + 8];
        al[mi][0] = *(const uint32_t*)&Al[r * LDA_ + kk + k04];
        al[mi][1] = *(const uint32_t*)&Al[(r + 8) * LDA_ + kk + k04];
        al[mi][2] = *(const uint32_t*)&Al[r * LDA_ + kk + k04 + 8];
        al[mi][3] = *(const uint32_t*)&Al[(r + 8) * LDA_ + kk + k04 + 8];
    }
    uint32_t bh[4][2], bl[4][2];
    #pragma unroll
    for (int nj = 0; nj < 4; nj++) {
        const int rn = wn * 32 + nj * 8 + g;
        bh[nj][0] = *(const uint32_t*)&Bh[rn * LDA_ + kk + k04];
        bh[nj][1] = *(const uint32_t*)&Bh[rn * LDA_ + kk + k04 + 8];
        bl[nj][0] = *(const uint32_t*)&Bl[rn * LDA_ + kk + k04];
        bl[nj][1] = *(const uint32_t*)&Bl[rn * LDA_ + kk + k04 + 8];
    }
    #pragma unroll
    for (int mi = 0; mi < 2; mi++)
        #pragma unroll
        for (int nj = 0; nj < 4; nj++) {
            mma16816(part[mi][nj], ah[mi], bh[nj]);
            mma16816(part[mi][nj], ah[mi], bl[nj]);
            mma16816(part[mi][nj], al[mi], bh[nj]);
        }
}

// ================== compress via mma.sync (split-bf16, 3 terms) ==================
__global__ __launch_bounds__(256, 1) void compress_mma_kernel() {
    extern __shared__ char smem[];
    const uint32_t sb = smem_to_u32(smem);
    const int tid = threadIdx.x, wid = tid >> 5, lane = tid & 31;
    const int wm = wid & 3, wn = wid >> 2;
    const int g = lane >> 2, k04 = (lane & 3) * 2;
    const int c0 = blockIdx.x * 64;
    const int t0 = blockIdx.y * 128;

    float* wsf = (float*)(smem + OFF_WS);
    for (int i = tid; i < 3 * NC_ * 128; i += 256) {
        const int rt = i >> 10, n = (i >> 7) & 7, row = i & 127;
        wsf[i] = g_W3[rt][t0 + row][n];
    }

    const int NIT = 8 * NC_;
    load_A(sb, g_Xhi, g_Xlo, D_, t0, 0, tid);
    load_B(sb, g_CNThi, g_CNTlo, D_, (size_t)0 * R_ + c0, 0, 0, tid);
    CP_COMMIT();
    load_B(sb, g_CNThi, g_CNTlo, D_, (size_t)1 * R_ + c0, 0, 1, tid);
    CP_COMMIT();

    float qa[2][4][4] = {}, ka[2][4][4] = {}, va[2][4][4] = {};
    const __nv_bfloat16* Ah = (const __nv_bfloat16*)(smem + OFF_AHI);
    const __nv_bfloat16* Al = (const __nv_bfloat16*)(smem + OFF_ALO);

    for (int it = 0; it < NIT; it++) {
        const int sc = it >> 3, n = it & 7, bb = it & 1;
        if (it != 0 && (it & 7) == 0) { CP_WAIT0(); } else { CP_WAIT1(); }
        __syncthreads();

        const __nv_bfloat16* Bh = (const __nv_bfloat16*)(smem + (bb ? OFF_B1H : OFF_B0H));
        const __nv_bfloat16* Bl = (const __nv_bfloat16*)(smem + (bb ? OFF_B1L : OFF_B0L));
        float part[2][4][4] = {};
        #pragma unroll
        for (int ks = 0; ks < 8; ks++)
            mma_step(Ah, Al, Bh, Bl, wm, wn, g, k04, ks * 16, part);

        #pragma unroll
        for (int mi = 0; mi < 2; mi++) {
            const int r0 = wm * 32 + mi * 16 + g;
            const float wq0 = wsf[0 * 1024 + n * 128 + r0], wq1 = wsf[0 * 1024 + n * 128 + r0 + 8];
            const float wk0 = wsf[1 * 1024 + n * 128 + r0], wk1 = wsf[1 * 1024 + n * 128 + r0 + 8];
            const float wv0 = wsf[2 * 1024 + n * 128 + r0], wv1 = wsf[2 * 1024 + n * 128 + r0 + 8];
            #pragma unroll
            for (int nj = 0; nj < 4; nj++) {
                qa[mi][nj][0] += wq0 * part[mi][nj][0]; qa[mi][nj][1] += wq0 * part[mi][nj][1];
                qa[mi][nj][2] += wq1 * part[mi][nj][2]; qa[mi][nj][3] += wq1 * part[mi][nj][3];
                ka[mi][nj][0] += wk0 * part[mi][nj][0]; ka[mi][nj][1] += wk0 * part[mi][nj][1];
                ka[mi][nj][2] += wk1 * part[mi][nj][2]; ka[mi][nj][3] += wk1 * part[mi][nj][3];
                va[mi][nj][0] += wv0 * part[mi][nj][0]; va[mi][nj][1] += wv0 * part[mi][nj][1];
                va[mi][nj][2] += wv1 * part[mi][nj][2]; va[mi][nj][3] += wv1 * part[mi][nj][3];
            }
        }
        __syncthreads();

        if (it + 1 < NIT) {
            if (((it + 1) & 7) == 0)
                load_A(sb, g_Xhi, g_Xlo, D_, t0, (sc + 1) * 128, tid);
            if (it + 2 < NIT) {
                const int sc2 = (it + 2) >> 3, n2 = (it + 2) & 7;
                load_B(sb, g_CNThi, g_CNTlo, D_, (size_t)n2 * R_ + c0, sc2 * 128, (it + 2) & 1, tid);
            }
            CP_COMMIT();
        }
    }

    #pragma unroll
    for (int mi = 0; mi < 2; mi++) {
        const int r0 = t0 + wm * 32 + mi * 16 + g;
        #pragma unroll
        for (int nj = 0; nj < 4; nj++) {
            const int cc = c0 + wn * 32 + nj * 8 + k04;
            *(float2*)&g_Q[(size_t)r0 * R_ + cc]       = make_float2(qa[mi][nj][0], qa[mi][nj][1]);
            *(float2*)&g_Q[(size_t)(r0 + 8) * R_ + cc] = make_float2(qa[mi][nj][2], qa[mi][nj][3]);
            *(float2*)&g_K[(size_t)r0 * R_ + cc]       = make_float2(ka[mi][nj][0], ka[mi][nj][1]);
            *(float2*)&g_K[(size_t)(r0 + 8) * R_ + cc] = make_float2(ka[mi][nj][2], ka[mi][nj][3]);
            *(float2*)&g_V[(size_t)r0 * R_ + cc]       = make_float2(va[mi][nj][0], va[mi][nj][1]);
            *(float2*)&g_V[(size_t)(r0 + 8) * R_ + cc] = make_float2(va[mi][nj][2], va[mi][nj][3]);
        }
    }
}

// ================== expand via mma.sync ==================
__global__ __launch_bounds__(256, 1) void expand_mma_kernel(float* __restrict__ out) {
    extern __shared__ char smem[];
    const uint32_t sb = smem_to_u32(smem);
    const int tid = threadIdx.x, wid = tid >> 5, lane = tid & 31;
    const int wm = wid & 3, wn = wid >> 2;
    const int g = lane >> 2, k04 = (lane & 3) * 2;
    const int c0 = blockIdx.x * 64;
    const int t0 = blockIdx.y * 128;

    float* wsf = (float*)(smem + OFF_WS);
    for (int i = tid; i < NE_ * 128; i += 256) {
        const int n = i >> 7, row = i & 127;
        wsf[i] = g_WO[t0 + row][n];
    }

    const int NIT = 4 * NE_;
    load_A(sb, g_AOhi, g_AOlo, R_, t0, 0, tid);
    load_B(sb, g_ENThi, g_ENTlo, R_, (size_t)0 * D_ + c0, 0, 0, tid);
    CP_COMMIT();
    load_B(sb, g_ENThi, g_ENTlo, R_, (size_t)1 * D_ + c0, 0, 1, tid);
    CP_COMMIT();

    float oa[2][4][4] = {};
    const __nv_bfloat16* Ah = (const __nv_bfloat16*)(smem + OFF_AHI);
    const __nv_bfloat16* Al = (const __nv_bfloat16*)(smem + OFF_ALO);

    for (int it = 0; it < NIT; it++) {
        const int sc = it >> 3, n = it & 7, bb = it & 1;
        if (it != 0 && (it & 7) == 0) { CP_WAIT0(); } else { CP_WAIT1(); }
        __syncthreads();

        const __nv_bfloat16* Bh = (const __nv_bfloat16*)(smem + (bb ? OFF_B1H : OFF_B0H));
        const __nv_bfloat16* Bl = (const __nv_bfloat16*)(smem + (bb ? OFF_B1L : OFF_B0L));
        float part[2][4][4] = {};
        #pragma unroll
        for (int ks = 0; ks < 8; ks++)
            mma_step(Ah, Al, Bh, Bl, wm, wn, g, k04, ks * 16, part);

        #pragma unroll
        for (int mi = 0; mi < 2; mi++) {
            const int r0 = wm * 32 + mi * 16 + g;
            const float w0 = wsf[n * 128 + r0], w1 = wsf[n * 128 + r0 + 8];
            #pragma unroll
            for (int nj = 0; nj < 4; nj++) {
                oa[mi][nj][0] += w0 * part[mi][nj][0]; oa[mi][nj][1] += w0 * part[mi][nj][1];
                oa[mi][nj][2] += w1 * part[mi][nj][2]; oa[mi][nj][3] += w1 * part[mi][nj][3];
            }
        }
        __syncthreads();

        if (it + 1 < NIT) {
            if (((it + 1) & 7) == 0)
                load_A(sb, g_AOhi, g_AOlo, R_, t0, (sc + 1) * 128, tid);
            if (it + 2 < NIT) {
                const int sc2 = (it + 2) >> 3, n2 = (it + 2) & 7;
                load_B(sb, g_ENThi, g_ENTlo, R_, (size_t)n2 * D_ + c0, sc2 * 128, (it + 2) & 1, tid);
            }
            CP_COMMIT();
        }
    }

    #pragma unroll
    for (int mi = 0; mi < 2; mi++) {
        const int r0 = t0 + wm * 32 + mi * 16 + g;
        #pragma unroll
        for (int nj = 0; nj < 4; nj++) {
            const int cc = c0 + wn * 32 + nj * 8 + k04;
            *(float2*)&out[(size_t)r0 * D_ + cc]       = make_float2(oa[mi][nj][0], oa[mi][nj][1]);
            *(float2*)&out[(size_t)(r0 + 8) * D_ + cc] = make_float2(oa[mi][nj][2], oa[mi][nj][3]);
        }
    }
}

// ================== causal flash attention on tensor cores ==================
// CTA: 128 q rows of one (b,h); 8 warps x 16 rows. K tiles of 64 tokens.
// Q/K staged [tok][dh] hi/lo; V staged transposed [dh][tok] hi/lo. Stride 70 halfs.
#define LDH_ 70
#define ATT_SMEM ((2*128 + 2*64 + 2*64) * LDH_ * 2)   /* 71680 bytes */

__global__ __launch_bounds__(256, 1) void attn_tc_kernel() {
    extern __shared__ char sm[];
    __nv_bfloat16* Qh = (__nv_bfloat16*)sm;            // [128][LDH_]
    __nv_bfloat16* Ql = Qh + 128 * LDH_;
    __nv_bfloat16* Kh = Ql + 128 * LDH_;               // [64][LDH_]
    __nv_bfloat16* Kl = Kh + 64 * LDH_;
    __nv_bfloat16* Vh = Kl + 64 * LDH_;                // [dh][tok]
    __nv_bfloat16* Vl = Vh + 64 * LDH_;

    const int qt = blockIdx.x, bhid = blockIdx.y;
    const int b = bhid >> 3, h = bhid & 7;
    const int q0 = qt * 128;
    const int tid = threadIdx.x, wid = tid >> 5, lane = tid & 31;
    const int g = lane >> 2, c01 = (lane & 3) * 2;
    const size_t rowbase = (size_t)(b * S_) * R_ + h * DH_;

    // ---- load Q (scaled by 1/sqrt(64)), split hi/lo ----
    for (int i = tid; i < 128 * 16; i += 256) {
        const int row = i >> 4, seg = i & 15;
        float4 v = *(const float4*)(g_Q + rowbase + (size_t)(q0 + row) * R_ + seg * 4);
        float xv[4] = {v.x * 0.125f, v.y * 0.125f, v.z * 0.125f, v.w * 0.125f};
        #pragma unroll
        for (int c2 = 0; c2 < 4; c2 += 2) {
            uint32_t hi, lo;
            pack_hilo(xv[c2], xv[c2 + 1], hi, lo);
            *(uint32_t*)&Qh[row * LDH_ + seg * 4 + c2] = hi;
            *(uint32_t*)&Ql[row * LDH_ + seg * 4 + c2] = lo;
        }
    }

    float o[8][4] = {};
    float m0 = -1e30f, m1 = -1e30f, l0 = 0.f, l1 = 0.f;
    const int rowlo = q0 + wid * 16;
    const int r0g = rowlo + g;
    const int nkt = (q0 >> 6) + 2;

    float4 pk[4], pv[4];
    #pragma unroll
    for (int j = 0; j < 4; j++) {
        const int linear = tid + j * 256;
        const int row = linear >> 4, seg = linear & 15;
        pk[j] = *(const float4*)(g_K + rowbase + (size_t)row * R_ + seg * 4);
        pv[j] = *(const float4*)(g_V + rowbase + (size_t)row * R_ + seg * 4);
    }

    for (int kt = 0; kt < nkt; kt++) {
        const int k0 = kt * 64;
        __syncthreads();
        // ---- stage K [tok][dh] and V transposed [dh][tok] ----
        #pragma unroll
        for (int j = 0; j < 4; j++) {
            const int linear = tid + j * 256;
            const int row = linear >> 4, seg = linear & 15;
            float kv[4] = {pk[j].x, pk[j].y, pk[j].z, pk[j].w};
            float vv[4] = {pv[j].x, pv[j].y, pv[j].z, pv[j].w};
            #pragma unroll
            for (int c2 = 0; c2 < 4; c2 += 2) {
                uint32_t hi, lo;
                pack_hilo(kv[c2], kv[c2 + 1], hi, lo);
                *(uint32_t*)&Kh[row * LDH_ + seg * 4 + c2] = hi;
                *(uint32_t*)&Kl[row * LDH_ + seg * 4 + c2] = lo;
            }
            #pragma unroll
            for (int c = 0; c < 4; c++) {
                const int dh = seg * 4 + c;
                __nv_bfloat16 vh = __float2bfloat16(vv[c]);
                Vh[dh * LDH_ + row] = vh;
                Vl[dh * LDH_ + row] = __float2bfloat16(vv[c] - __bfloat162float(vh));
            }
        }
        __syncthreads();
        // prefetch next tile
        if (kt + 1 < nkt) {
            const int kn = k0 + 64;
            #pragma unroll
            for (int j = 0; j < 4; j++) {
                const int linear = tid + j * 256;
                const int row = linear >> 4, seg = linear & 15;
                pk[j] = *(const float4*)(g_K + rowbase + (size_t)(kn + row) * R_ + seg * 4);
                pv[j] = *(const float4*)(g_V + rowbase + (size_t)(kn + row) * R_ + seg * 4);
            }
        }

        if (k0 <= rowlo + 15) {
            // ---- S = Q K^T (3-term split) ----
            float s[8][4] = {};
            #pragma unroll
            for (int kc = 0; kc < 4; kc++) {
                const int kk = kc * 16 + c01;
                const int ra = wid * 16 + g;
                uint32_t aH[4], aL[4];
                aH[0] = *(const uint32_t*)&Qh[ra * LDH_ + kk];
                aH[1] = *(const uint32_t*)&Qh[(ra + 8) * LDH_ + kk];
                aH[2] = *(const uint32_t*)&Qh[ra * LDH_ + kk + 8];
                aH[3] = *(const uint32_t*)&Qh[(ra + 8) * LDH_ + kk + 8];
                aL[0] = *(const uint32_t*)&Ql[ra * LDH_ + kk];
                aL[1] = *(const uint32_t*)&Ql[(ra + 8) * LDH_ + kk];
                aL[2] = *(const uint32_t*)&Ql[ra * LDH_ + kk + 8];
                aL[3] = *(const uint32_t*)&Ql[(ra + 8) * LDH_ + kk + 8];
                #pragma unroll
                for (int nj = 0; nj < 8; nj++) {
                    const int rn = nj * 8 + g;
                    uint32_t bH[2] = {*(const uint32_t*)&Kh[rn * LDH_ + kk],
                                      *(const uint32_t*)&Kh[rn * LDH_ + kk + 8]};
                    uint32_t bL[2] = {*(const uint32_t*)&Kl[rn * LDH_ + kk],
                                      *(const uint32_t*)&Kl[rn * LDH_ + kk + 8]};
                    mma16816(s[nj], aH, bH);
                    mma16816(s[nj], aH, bL);
                    mma16816(s[nj], aL, bH);
                }
            }
            // ---- causal mask (diag tiles only) ----
            if (k0 + 63 > rowlo) {
                #pragma unroll
                for (int nj = 0; nj < 8; nj++) {
                    const int tok = k0 + nj * 8 + c01;
                    if (tok > r0g)         s[nj][0] = -1e30f;
                    if (tok + 1 > r0g)     s[nj][1] = -1e30f;
                    if (tok > r0g + 8)     s[nj][2] = -1e30f;
                    if (tok + 1 > r0g + 8) s[nj][3] = -1e30f;
                }
            }
            // ---- online softmax (rows fully in-warp; quad reduce) ----
            float rm0 = -1e30f, rm1 = -1e30f;
            #pragma unroll
            for (int nj = 0; nj < 8; nj++) {
                rm0 = fmaxf(rm0, fmaxf(s[nj][0], s[nj][1]));
                rm1 = fmaxf(rm1, fmaxf(s[nj][2], s[nj][3]));
            }
            rm0 = fmaxf(rm0, __shfl_xor_sync(0xffffffffu, rm0, 1));
            rm0 = fmaxf(rm0, __shfl_xor_sync(0xffffffffu, rm0, 2));
            rm1 = fmaxf(rm1, __shfl_xor_sync(0xffffffffu, rm1, 1));
            rm1 = fmaxf(rm1, __shfl_xor_sync(0xffffffffu, rm1, 2));
            const float nm0 = fmaxf(m0, rm0), nm1 = fmaxf(m1, rm1);
            const float sc0 = __expf(m0 - nm0), sc1 = __expf(m1 - nm1);
            m0 = nm0; m1 = nm1;
            float rs0 = 0.f, rs1 = 0.f;
            #pragma unroll
            for (int nj = 0; nj < 8; nj++) {
                s[nj][0] = __expf(s[nj][0] - nm0);
                s[nj][1] = __expf(s[nj][1] - nm0);
                s[nj][2] = __expf(s[nj][2] - nm1);
                s[nj][3] = __expf(s[nj][3] - nm1);
                rs0 += s[nj][0] + s[nj][1];
                rs1 += s[nj][2] + s[nj][3];
            }
            rs0 += __shfl_xor_sync(0xffffffffu, rs0, 1);
            rs0 += __shfl_xor_sync(0xffffffffu, rs0, 2);
            rs1 += __shfl_xor_sync(0xffffffffu, rs1, 1);
            rs1 += __shfl_xor_sync(0xffffffffu, rs1, 2);
            l0 = l0 * sc0 + rs0;
            l1 = l1 * sc1 + rs1;
            #pragma unroll
            for (int nj = 0; nj < 8; nj++) {
                o[nj][0] *= sc0; o[nj][1] *= sc0;
                o[nj][2] *= sc1; o[nj][3] *= sc1;
            }
            // ---- O += P V (P packed from regs, 3-term split) ----
            #pragma unroll
            for (int kc = 0; kc < 4; kc++) {
                uint32_t aH[4], aL[4];
                pack_hilo(s[2 * kc][0],     s[2 * kc][1],     aH[0], aL[0]);
                pack_hilo(s[2 * kc][2],     s[2 * kc][3],     aH[1], aL[1]);
                pack_hilo(s[2 * kc + 1][0], s[2 * kc + 1][1], aH[2], aL[2]);
                pack_hilo(s[2 * kc + 1][2], s[2 * kc + 1][3], aH[3], aL[3]);
                const int kk = kc * 16 + c01;
                #pragma unroll
                for (int nj = 0; nj < 8; nj++) {
                    const int rn = nj * 8 + g;
                    uint32_t bH[2] = {*(const uint32_t*)&Vh[rn * LDH_ + kk],
                                      *(const uint32_t*)&Vh[rn * LDH_ + kk + 8]};
                    uint32_t bL[2] = {*(const uint32_t*)&Vl[rn * LDH_ + kk],
                                      *(const uint32_t*)&Vl[rn * LDH_ + kk + 8]};
                    mma16816(o[nj], aH, bH);
                    mma16816(o[nj], aH, bL);
                    mma16816(o[nj], aL, bH);
                }
            }
        }
    }
    // ---- epilogue ----
    const float inv0 = 1.f / l0, inv1 = 1.f / l1;
    #pragma unroll
    for (int nj = 0; nj < 8; nj++) {
        const int cc = h * DH_ + nj * 8 + c01;
        *(float2*)&g_AO[(size_t)(b * S_ + r0g) * R_ + cc] =
            make_float2(o[nj][0] * inv0, o[nj][1] * inv0);
        *(float2*)&g_AO[(size_t)(b * S_ + r0g + 8) * R_ + cc] =
            make_float2(o[nj][2] * inv1, o[nj][3] * inv1);
    }
}

// ================== output router ==================
__global__ void router_o_kernel(const float* __restrict__ wo) {
    __shared__ float as[R_];
    __shared__ float logits[NE_];
    const int t = blockIdx.x;
    for (int i = threadIdx.x; i < R_; i += 256) as[i] = g_AO[(size_t)t * R_ + i];
    __syncthreads();
    const int warp = threadIdx.x >> 5, lane = threadIdx.x & 31;
    const float* w = wo + warp * R_;
    float s = 0.f;
    for (int r = lane; r < R_; r += 32) s += as[r] * w[r];
    #pragma unroll
    for (int o = 16; o > 0; o >>= 1) s += __shfl_xor_sync(0xffffffffu, s, o);
    if (lane == 0) logits[warp] = s;
    __syncthreads();
    if (threadIdx.x == 0) {
        float m = -1e30f;
        for (int n = 0; n < NE_; n++) m = fmaxf(m, logits[n]);
        float e[NE_], sum = 0.f;
        for (int n = 0; n < NE_; n++) { e[n] = expf(logits[n] - m); sum += e[n]; }
        const float inv = 1.f / sum;
        for (int n = 0; n < NE_; n++) g_WO[t][n] = e[n] * inv;
    }
}

__global__ void split_ao_kernel(size_t n4) {
    size_t i = (size_t)blockIdx.x * blockDim.x + threadIdx.x;
    if (i >= n4) return;
    float4 x = ((const float4*)g_AO)[i];
    float xv[4] = {x.x, x.y, x.z, x.w};
    bf4 h, l;
    #pragma unroll
    for (int j = 0; j < 4; j++) {
        h.v[j] = __float2bfloat16(xv[j]);
        l.v[j] = __float2bfloat16(xv[j] - __bfloat162float(h.v[j]));
    }
    ((bf4*)g_AOhi)[i] = h;
    ((bf4*)g_AOlo)[i] = l;
}

// ================== launch ==================
extern "C" void kernel_launch(void* const* d_in, const int* in_sizes, int n_in,
                              void* d_out, int out_size) {
    const float* x  = (const float*)d_in[0];
    const float* cn = (const float*)d_in[2];
    const float* en = (const float*)d_in[3];
    const float* wq = (const float*)d_in[4];
    const float* wk = (const float*)d_in[5];
    const float* wv = (const float*)d_in[6];
    const float* wo = (const float*)d_in[7];
    float* out = (float*)d_out;

    cudaFuncSetAttribute((const void*)compress_mma_kernel,
                         cudaFuncAttributeMaxDynamicSharedMemorySize, MSMEM_TOTAL);
    cudaFuncSetAttribute((const void*)expand_mma_kernel,
                         cudaFuncAttributeMaxDynamicSharedMemorySize, MSMEM_TOTAL);
    cudaFuncSetAttribute((const void*)attn_tc_kernel,
                         cudaFuncAttributeMaxDynamicSharedMemorySize, ATT_SMEM);

    __nv_bfloat16 *xhi, *xlo, *cnthi, *cntlo, *enthi, *entlo;
    cudaGetSymbolAddress((void**)&xhi, g_Xhi);
    cudaGetSymbolAddress((void**)&xlo, g_Xlo);
    cudaGetSymbolAddress((void**)&cnthi, g_CNThi);
    cudaGetSymbolAddress((void**)&cntlo, g_CNTlo);
    cudaGetSymbolAddress((void**)&enthi, g_ENThi);
    cudaGetSymbolAddress((void**)&entlo, g_ENTlo);

    // prep
    split_bf16_kernel<<<(unsigned)((size_t)T_*D_/4/256), 256>>>(x, xhi, xlo, (size_t)T_*D_/4);
    transpose_split_kernel<<<dim3(R_/32, D_/32, NC_), dim3(32, 8)>>>(cn, cnthi, cntlo, D_, R_);
    transpose_split_kernel<<<dim3(D_/32, R_/32, NE_), dim3(32, 8)>>>(en, enthi, entlo, R_, D_);
    router3_kernel<<<T_, 256>>>(x, wq, wk, wv);
    // main pipeline
    compress_mma_kernel<<<dim3(R_/64, T_/128), 256, MSMEM_TOTAL>>>();
    attn_tc_kernel<<<dim3(S_/128, B_*H_), 256, ATT_SMEM>>>();
    router_o_kernel<<<T_, 256>>>(wo);
    split_ao_kernel<<<(unsigned)((size_t)T_*R_/4/256), 256>>>((size_t)T_*R_/4);
    expand_mma_kernel<<<dim3(D_/64, T_/128), 256, MSMEM_TOTAL>>>(out);
}

// round 14
// speedup vs baseline: 3.8631x; 1.0888x over previous
#include <cuda_runtime.h>
#include <cuda_bf16.h>
#include <math.h>
#include <stdint.h>

#define B_  4
#define S_  2048
#define D_  1024
#define R_  512
#define H_  8
#define DH_ 64
#define NC_ 8
#define NE_ 8
#define T_  (B_*S_)   // 8192 tokens

// ================= helpers =================
__device__ __forceinline__ uint32_t smem_to_u32(const void* p) {
    uint32_t a;
    asm("{ .reg .u64 t; cvta.to.shared.u64 t, %1; cvt.u32.u64 %0, t; }" : "=r"(a) : "l"(p));
    return a;
}
__device__ __forceinline__ void cpa16(uint32_t dst, const void* src) {
    asm volatile("cp.async.cg.shared.global [%0], [%1], 16;" :: "r"(dst), "l"(src));
}
#define CP_COMMIT() asm volatile("cp.async.commit_group;" ::: "memory")
#define CP_WAIT0()  asm volatile("cp.async.wait_group 0;" ::: "memory")
#define CP_WAIT1()  asm volatile("cp.async.wait_group 1;" ::: "memory")

// m16n8k16 bf16 MMA, f32 accum, A row-major, B col-major
__device__ __forceinline__ void mma16816(float* c, const uint32_t* a, const uint32_t* b) {
    asm volatile("mma.sync.aligned.m16n8k16.row.col.f32.bf16.bf16.f32 "
        "{%0,%1,%2,%3}, {%4,%5,%6,%7}, {%8,%9}, {%0,%1,%2,%3};"
        : "+f"(c[0]), "+f"(c[1]), "+f"(c[2]), "+f"(c[3])
        : "r"(a[0]), "r"(a[1]), "r"(a[2]), "r"(a[3]), "r"(b[0]), "r"(b[1]));
}
// m16n8k8 tf32 MMA
__device__ __forceinline__ void mma16808(float* c, const uint32_t* a, const uint32_t* b) {
    asm volatile("mma.sync.aligned.m16n8k8.row.col.f32.tf32.tf32.f32 "
        "{%0,%1,%2,%3}, {%4,%5,%6,%7}, {%8,%9}, {%0,%1,%2,%3};"
        : "+f"(c[0]), "+f"(c[1]), "+f"(c[2]), "+f"(c[3])
        : "r"(a[0]), "r"(a[1]), "r"(a[2]), "r"(a[3]), "r"(b[0]), "r"(b[1]));
}
__device__ __forceinline__ float tf32r(float x) {
    uint32_t u;
    asm("cvt.rna.tf32.f32 %0, %1;" : "=r"(u) : "f"(x));
    return __uint_as_float(u);
}
// pack two floats into bf16x2 hi + residual lo
__device__ __forceinline__ void pack_hilo(float x, float y, uint32_t& hi, uint32_t& lo) {
    __nv_bfloat16 hx = __float2bfloat16(x), hy = __float2bfloat16(y);
    __nv_bfloat162 hv; hv.x = hx; hv.y = hy;
    hi = *(uint32_t*)&hv;
    __nv_bfloat162 lv;
    lv.x = __float2bfloat16(x - __bfloat162float(hx));
    lv.y = __float2bfloat16(y - __bfloat162float(hy));
    lo = *(uint32_t*)&lv;
}

// ---------------- scratch (no allocations allowed) ----------------
__device__ float g_W3[3][T_][NC_];
__device__ float g_Q[(size_t)T_*R_];
__device__ float g_K[(size_t)T_*R_];
__device__ float g_V[(size_t)T_*R_];
__device__ float g_AO[(size_t)T_*R_];      // tf32-rounded by attn epilogue
__device__ float g_WO[T_][NE_];
__device__ __nv_bfloat16 g_Xhi[(size_t)T_*D_],  g_Xlo[(size_t)T_*D_];
__device__ __nv_bfloat16 g_CNThi[(size_t)NC_*R_*D_], g_CNTlo[(size_t)NC_*R_*D_]; // [n][r][d]
__device__ float g_ENT[(size_t)NE_*D_*R_]; // [n][d][r], tf32-rounded fp32

// ================= prep: fp32 -> bf16 hi/lo split =================
struct bf4 { __nv_bfloat16 v[4]; };
__global__ void split_bf16_kernel(const float* __restrict__ in,
                                  __nv_bfloat16* __restrict__ oh,
                                  __nv_bfloat16* __restrict__ ol, size_t n4) {
    size_t i = (size_t)blockIdx.x * blockDim.x + threadIdx.x;
    if (i >= n4) return;
    float4 x = ((const float4*)in)[i];
    float xv[4] = {x.x, x.y, x.z, x.w};
    bf4 h, l;
    #pragma unroll
    for (int j = 0; j < 4; j++) {
        h.v[j] = __float2bfloat16(xv[j]);
        l.v[j] = __float2bfloat16(xv[j] - __bfloat162float(h.v[j]));
    }
    ((bf4*)oh)[i] = h;
    ((bf4*)ol)[i] = l;
}

// ===== prep: transpose [n][DIN][DOUT] fp32 -> [n][DOUT][DIN] bf16 hi/lo =====
__global__ void transpose_split_kernel(const float* __restrict__ in,
                                       __nv_bfloat16* __restrict__ oh,
                                       __nv_bfloat16* __restrict__ ol,
                                       int DIN, int DOUT) {
    __shared__ float ts[32][33];
    const int n = blockIdx.z;
    const float* src = in + (size_t)n * DIN * DOUT;
    const int r0 = blockIdx.x * 32, d0 = blockIdx.y * 32;
    for (int k = threadIdx.y; k < 32; k += 8)
        ts[k][threadIdx.x] = src[(size_t)(d0 + k) * DOUT + r0 + threadIdx.x];
    __syncthreads();
    const size_t obase = (size_t)n * DIN * DOUT;
    for (int k = threadIdx.y; k < 32; k += 8) {
        float v = ts[threadIdx.x][k];
        size_t o = obase + (size_t)(r0 + k) * DIN + d0 + threadIdx.x;
        __nv_bfloat16 h = __float2bfloat16(v);
        oh[o] = h;
        ol[o] = __float2bfloat16(v - __bfloat162float(h));
    }
}

// ===== prep: transpose [n][DIN][DOUT] fp32 -> [n][DOUT][DIN] tf32-rounded fp32 =====
__global__ void transpose_tf32_kernel(const float* __restrict__ in,
                                      float* __restrict__ o32,
                                      int DIN, int DOUT) {
    __shared__ float ts[32][33];
    const int n = blockIdx.z;
    const float* src = in + (size_t)n * DIN * DOUT;
    const int r0 = blockIdx.x * 32, d0 = blockIdx.y * 32;
    for (int k = threadIdx.y; k < 32; k += 8)
        ts[k][threadIdx.x] = src[(size_t)(d0 + k) * DOUT + r0 + threadIdx.x];
    __syncthreads();
    const size_t obase = (size_t)n * DIN * DOUT;
    for (int k = threadIdx.y; k < 32; k += 8) {
        float v = ts[threadIdx.x][k];
        size_t o = obase + (size_t)(r0 + k) * DIN + d0 + threadIdx.x;
        o32[o] = tf32r(v);
    }
}

// ================== router q/k/v (float4 vectorized) ==================
__global__ void router3_kernel(const float* __restrict__ x,
                               const float* __restrict__ wq,
                               const float* __restrict__ wk,
                               const float* __restrict__ wv) {
    __shared__ float4 xs4[D_/4];
    __shared__ float logits[3][NC_];
    const int t = blockIdx.x;
    const float4* xr = (const float4*)(x + (size_t)t * D_);
    for (int i = threadIdx.x; i < D_/4; i += 256) xs4[i] = xr[i];
    __syncthreads();
    const int warp = threadIdx.x >> 5, lane = threadIdx.x & 31;
    const float* wr[3] = {wq, wk, wv};
    for (int rt = 0; rt < 3; rt++) {
        const float4* w4 = (const float4*)(wr[rt] + warp * D_);
        float s = 0.f;
        #pragma unroll
        for (int d = lane; d < D_/4; d += 32) {
            const float4 a = xs4[d], b = w4[d];
            s += a.x*b.x + a.y*b.y + a.z*b.z + a.w*b.w;
        }
        #pragma unroll
        for (int o = 16; o > 0; o >>= 1) s += __shfl_xor_sync(0xffffffffu, s, o);
        if (lane == 0) logits[rt][warp] = s;
    }
    __syncthreads();
    if (threadIdx.x < 3) {
        const int rt = threadIdx.x;
        float m = -1e30f;
        for (int n = 0; n < NC_; n++) m = fmaxf(m, logits[rt][n]);
        float e[NC_], sum = 0.f;
        for (int n = 0; n < NC_; n++) { e[n] = expf(logits[rt][n] - m); sum += e[n]; }
        const float inv = 1.f / sum;
        for (int n = 0; n < NC_; n++) g_W3[rt][t][n] = e[n] * inv;
    }
}

// ============== SMEM layout for the bf16 compress GEMM (bytes) ==============
#define LDA_   136
#define OFF_WS   0
#define OFF_AHI  12288
#define OFF_ALO  (OFF_AHI + 128*LDA_*2)
#define OFF_B0H  (OFF_ALO + 128*LDA_*2)
#define OFF_B0L  (OFF_B0H + 64*LDA_*2)
#define OFF_B1H  (OFF_B0L + 64*LDA_*2)
#define OFF_B1L  (OFF_B1H + 64*LDA_*2)
#define MSMEM_TOTAL (OFF_B1L + 64*LDA_*2)

__device__ __forceinline__ void load_A(uint32_t sb, const __nv_bfloat16* Ahi,
                                       const __nv_bfloat16* Alo, size_t rowstride,
                                       int t0, int kbase, int tid) {
    for (int i = tid; i < 128 * 16; i += 256) {
        const int row = i >> 4, seg = i & 15;
        const uint32_t doff = (uint32_t)(row * LDA_ + seg * 8) * 2;
        const size_t soff = (size_t)(t0 + row) * rowstride + kbase + seg * 8;
        cpa16(sb + OFF_AHI + doff, Ahi + soff);
        cpa16(sb + OFF_ALO + doff, Alo + soff);
    }
}
__device__ __forceinline__ void load_B(uint32_t sb, const __nv_bfloat16* Bhi,
                                       const __nv_bfloat16* Blo, size_t rowstride,
                                       size_t rbase, int kbase, int bb, int tid) {
    const uint32_t oh = bb ? OFF_B1H : OFF_B0H;
    const uint32_t ol = bb ? OFF_B1L : OFF_B0L;
    for (int i = tid; i < 64 * 16; i += 256) {
        const int row = i >> 4, seg = i & 15;
        const uint32_t doff = (uint32_t)(row * LDA_ + seg * 8) * 2;
        const size_t soff = (rbase + row) * rowstride + kbase + seg * 8;
        cpa16(sb + oh + doff, Bhi + soff);
        cpa16(sb + ol + doff, Blo + soff);
    }
}

__device__ __forceinline__ void mma_step(const __nv_bfloat16* Ah, const __nv_bfloat16* Al,
                                         const __nv_bfloat16* Bh, const __nv_bfloat16* Bl,
                                         int wm, int wn, int g, int k04, int kk,
                                         float part[2][4][4]) {
    uint32_t ah[2][4], al[2][4];
    #pragma unroll
    for (int mi = 0; mi < 2; mi++) {
        const int r = wm * 32 + mi * 16 + g;
        ah[mi][0] = *(const uint32_t*)&Ah[r * LDA_ + kk + k04];
        ah[mi][1] = *(const uint32_t*)&Ah[(r + 8) * LDA_ + kk + k04];
        ah[mi][2] = *(const uint32_t*)&Ah[r * LDA_ + kk + k04 + 8];
        ah[mi][3] = *(const uint32_t*)&Ah[(r + 8) * LDA_ + kk + k04 + 8];
        al[mi][0] = *(const uint32_t*)&Al[r * LDA_ + kk + k04];
        al[mi][1] = *(const uint32_t*)&Al[(r + 8) * LDA_ + kk + k04];
        al[mi][2] = *(const uint32_t*)&Al[r * LDA_ + kk + k04 + 8];
        al[mi][3] = *(const uint32_t*)&Al[(r + 8) * LDA_ + kk + k04 + 8];
    }
    uint32_t bh[4][2], bl[4][2];
    #pragma unroll
    for (int nj = 0; nj < 4; nj++) {
        const int rn = wn * 32 + nj * 8 + g;
        bh[nj][0] = *(const uint32_t*)&Bh[rn * LDA_ + kk + k04];
        bh[nj][1] = *(const uint32_t*)&Bh[rn * LDA_ + kk + k04 + 8];
        bl[nj][0] = *(const uint32_t*)&Bl[rn * LDA_ + kk + k04];
        bl[nj][1] = *(const uint32_t*)&Bl[rn * LDA_ + kk + k04 + 8];
    }
    #pragma unroll
    for (int mi = 0; mi < 2; mi++)
        #pragma unroll
        for (int nj = 0; nj < 4; nj++) {
            mma16816(part[mi][nj], ah[mi], bh[nj]);
            mma16816(part[mi][nj], ah[mi], bl[nj]);
            mma16816(part[mi][nj], al[mi], bh[nj]);
        }
}

// ================== compress via mma.sync (split-bf16, 3 terms) ==================
__global__ __launch_bounds__(256, 1) void compress_mma_kernel() {
    extern __shared__ char smem[];
    const uint32_t sb = smem_to_u32(smem);
    const int tid = threadIdx.x, wid = tid >> 5, lane = tid & 31;
    const int wm = wid & 3, wn = wid >> 2;
    const int g = lane >> 2, k04 = (lane & 3) * 2;
    const int c0 = blockIdx.x * 64;
    const int t0 = blockIdx.y * 128;

    float* wsf = (float*)(smem + OFF_WS);
    for (int i = tid; i < 3 * NC_ * 128; i += 256) {
        const int rt = i >> 10, n = (i >> 7) & 7, row = i & 127;
        wsf[i] = g_W3[rt][t0 + row][n];
    }

    const int NIT = 8 * NC_;
    load_A(sb, g_Xhi, g_Xlo, D_, t0, 0, tid);
    load_B(sb, g_CNThi, g_CNTlo, D_, (size_t)0 * R_ + c0, 0, 0, tid);
    CP_COMMIT();
    load_B(sb, g_CNThi, g_CNTlo, D_, (size_t)1 * R_ + c0, 0, 1, tid);
    CP_COMMIT();

    float qa[2][4][4] = {}, ka[2][4][4] = {}, va[2][4][4] = {};
    const __nv_bfloat16* Ah = (const __nv_bfloat16*)(smem + OFF_AHI);
    const __nv_bfloat16* Al = (const __nv_bfloat16*)(smem + OFF_ALO);

    for (int it = 0; it < NIT; it++) {
        const int sc = it >> 3, n = it & 7, bb = it & 1;
        if (it != 0 && (it & 7) == 0) { CP_WAIT0(); } else { CP_WAIT1(); }
        __syncthreads();

        const __nv_bfloat16* Bh = (const __nv_bfloat16*)(smem + (bb ? OFF_B1H : OFF_B0H));
        const __nv_bfloat16* Bl = (const __nv_bfloat16*)(smem + (bb ? OFF_B1L : OFF_B0L));
        float part[2][4][4] = {};
        #pragma unroll
        for (int ks = 0; ks < 8; ks++)
            mma_step(Ah, Al, Bh, Bl, wm, wn, g, k04, ks * 16, part);

        #pragma unroll
        for (int mi = 0; mi < 2; mi++) {
            const int r0 = wm * 32 + mi * 16 + g;
            const float wq0 = wsf[0 * 1024 + n * 128 + r0], wq1 = wsf[0 * 1024 + n * 128 + r0 + 8];
            const float wk0 = wsf[1 * 1024 + n * 128 + r0], wk1 = wsf[1 * 1024 + n * 128 + r0 + 8];
            const float wv0 = wsf[2 * 1024 + n * 128 + r0], wv1 = wsf[2 * 1024 + n * 128 + r0 + 8];
            #pragma unroll
            for (int nj = 0; nj < 4; nj++) {
                qa[mi][nj][0] += wq0 * part[mi][nj][0]; qa[mi][nj][1] += wq0 * part[mi][nj][1];
                qa[mi][nj][2] += wq1 * part[mi][nj][2]; qa[mi][nj][3] += wq1 * part[mi][nj][3];
                ka[mi][nj][0] += wk0 * part[mi][nj][0]; ka[mi][nj][1] += wk0 * part[mi][nj][1];
                ka[mi][nj][2] += wk1 * part[mi][nj][2]; ka[mi][nj][3] += wk1 * part[mi][nj][3];
                va[mi][nj][0] += wv0 * part[mi][nj][0]; va[mi][nj][1] += wv0 * part[mi][nj][1];
                va[mi][nj][2] += wv1 * part[mi][nj][2]; va[mi][nj][3] += wv1 * part[mi][nj][3];
            }
        }
        __syncthreads();

        if (it + 1 < NIT) {
            if (((it + 1) & 7) == 0)
                load_A(sb, g_Xhi, g_Xlo, D_, t0, (sc + 1) * 128, tid);
            if (it + 2 < NIT) {
                const int sc2 = (it + 2) >> 3, n2 = (it + 2) & 7;
                load_B(sb, g_CNThi, g_CNTlo, D_, (size_t)n2 * R_ + c0, sc2 * 128, (it + 2) & 1, tid);
            }
            CP_COMMIT();
        }
    }

    #pragma unroll
    for (int mi = 0; mi < 2; mi++) {
        const int r0 = t0 + wm * 32 + mi * 16 + g;
        #pragma unroll
        for (int nj = 0; nj < 4; nj++) {
            const int cc = c0 + wn * 32 + nj * 8 + k04;
            *(float2*)&g_Q[(size_t)r0 * R_ + cc]       = make_float2(qa[mi][nj][0], qa[mi][nj][1]);
            *(float2*)&g_Q[(size_t)(r0 + 8) * R_ + cc] = make_float2(qa[mi][nj][2], qa[mi][nj][3]);
            *(float2*)&g_K[(size_t)r0 * R_ + cc]       = make_float2(ka[mi][nj][0], ka[mi][nj][1]);
            *(float2*)&g_K[(size_t)(r0 + 8) * R_ + cc] = make_float2(ka[mi][nj][2], ka[mi][nj][3]);
            *(float2*)&g_V[(size_t)r0 * R_ + cc]       = make_float2(va[mi][nj][0], va[mi][nj][1]);
            *(float2*)&g_V[(size_t)(r0 + 8) * R_ + cc] = make_float2(va[mi][nj][2], va[mi][nj][3]);
        }
    }
}

// ============== expand via tf32 mma (single pass, pre-rounded operands) ==============
// SMEM: fp32 tiles, stride 132 floats (conflict-free for tf32 frag patterns)
#define LDE_ 132
#define EOFF_WS 0
#define EOFF_A  16384
#define EOFF_B0 (EOFF_A + 128*LDE_*4)
#define EOFF_B1 (EOFF_B0 + 64*LDE_*4)
#define ESMEM_TOTAL (EOFF_B1 + 64*LDE_*4)   /* 151552 */

__device__ __forceinline__ void load_Af32(uint32_t sb, const float* A, size_t rowstride,
                                          int t0, int kbase, int tid) {
    for (int i = tid; i < 128 * 32; i += 256) {
        const int row = i >> 5, seg = i & 31;
        const uint32_t doff = (uint32_t)(row * LDE_ + seg * 4) * 4;
        const size_t soff = (size_t)(t0 + row) * rowstride + kbase + seg * 4;
        cpa16(sb + EOFF_A + doff, A + soff);
    }
}
__device__ __forceinline__ void load_Bf32(uint32_t sb, const float* Bsrc, size_t rowstride,
                                          size_t rbase, int kbase, int bb, int tid) {
    const uint32_t ob = bb ? EOFF_B1 : EOFF_B0;
    for (int i = tid; i < 64 * 32; i += 256) {
        const int row = i >> 5, seg = i & 31;
        const uint32_t doff = (uint32_t)(row * LDE_ + seg * 4) * 4;
        const size_t soff = (rbase + row) * rowstride + kbase + seg * 4;
        cpa16(sb + ob + doff, Bsrc + soff);
    }
}

__global__ __launch_bounds__(256, 1) void expand_mma_kernel(float* __restrict__ out) {
    extern __shared__ char smem[];
    const uint32_t sb = smem_to_u32(smem);
    const int tid = threadIdx.x, wid = tid >> 5, lane = tid & 31;
    const int wm = wid & 3, wn = wid >> 2;
    const int g = lane >> 2, c4 = lane & 3, k04 = c4 * 2;
    const int c0 = blockIdx.x * 64;      // d tile
    const int t0 = blockIdx.y * 128;     // token tile

    float* wsf = (float*)(smem + EOFF_WS);
    for (int i = tid; i < NE_ * 128; i += 256) {
        const int n = i >> 7, row = i & 127;
        wsf[i] = g_WO[t0 + row][n];
    }

    const int NIT = 4 * NE_;  // 4 superchunks (K=512) x 8 neurons
    load_Af32(sb, g_AO, R_, t0, 0, tid);
    load_Bf32(sb, g_ENT, R_, (size_t)0 * D_ + c0, 0, 0, tid);
    CP_COMMIT();
    load_Bf32(sb, g_ENT, R_, (size_t)1 * D_ + c0, 0, 1, tid);
    CP_COMMIT();

    float oa[2][4][4] = {};
    const uint32_t* As = (const uint32_t*)(smem + EOFF_A);

    for (int it = 0; it < NIT; it++) {
        const int sc = it >> 3, n = it & 7, bb = it & 1;
        if (it != 0 && (it & 7) == 0) { CP_WAIT0(); } else { CP_WAIT1(); }
        __syncthreads();

        const uint32_t* Bs = (const uint32_t*)(smem + (bb ? EOFF_B1 : EOFF_B0));
        float part[2][4][4] = {};
        #pragma unroll
        for (int ks = 0; ks < 16; ks++) {
            const int k8 = ks * 8;
            uint32_t a[2][4];
            #pragma unroll
            for (int mi = 0; mi < 2; mi++) {
                const int r = wm * 32 + mi * 16 + g;
                a[mi][0] = As[r * LDE_ + k8 + c4];
                a[mi][1] = As[(r + 8) * LDE_ + k8 + c4];
                a[mi][2] = As[r * LDE_ + k8 + c4 + 4];
                a[mi][3] = As[(r + 8) * LDE_ + k8 + c4 + 4];
            }
            uint32_t b[4][2];
            #pragma unroll
            for (int nj = 0; nj < 4; nj++) {
                const int rn = wn * 32 + nj * 8 + g;
                b[nj][0] = Bs[rn * LDE_ + k8 + c4];
                b[nj][1] = Bs[rn * LDE_ + k8 + c4 + 4];
            }
            #pragma unroll
            for (int mi = 0; mi < 2; mi++)
                #pragma unroll
                for (int nj = 0; nj < 4; nj++)
                    mma16808(part[mi][nj], a[mi], b[nj]);
        }

        #pragma unroll
        for (int mi = 0; mi < 2; mi++) {
            const int r0 = wm * 32 + mi * 16 + g;
            const float w0 = wsf[n * 128 + r0], w1 = wsf[n * 128 + r0 + 8];
            #pragma unroll
            for (int nj = 0; nj < 4; nj++) {
                oa[mi][nj][0] += w0 * part[mi][nj][0]; oa[mi][nj][1] += w0 * part[mi][nj][1];
                oa[mi][nj][2] += w1 * part[mi][nj][2]; oa[mi][nj][3] += w1 * part[mi][nj][3];
            }
        }
        __syncthreads();

        if (it + 1 < NIT) {
            if (((it + 1) & 7) == 0)
                load_Af32(sb, g_AO, R_, t0, (sc + 1) * 128, tid);
            if (it + 2 < NIT) {
                const int sc2 = (it + 2) >> 3, n2 = (it + 2) & 7;
                load_Bf32(sb, g_ENT, R_, (size_t)n2 * D_ + c0, sc2 * 128, (it + 2) & 1, tid);
            }
            CP_COMMIT();
        }
    }

    #pragma unroll
    for (int mi = 0; mi < 2; mi++) {
        const int r0 = t0 + wm * 32 + mi * 16 + g;
        #pragma unroll
        for (int nj = 0; nj < 4; nj++) {
            const int cc = c0 + wn * 32 + nj * 8 + k04;
            *(float2*)&out[(size_t)r0 * D_ + cc]       = make_float2(oa[mi][nj][0], oa[mi][nj][1]);
            *(float2*)&out[(size_t)(r0 + 8) * D_ + cc] = make_float2(oa[mi][nj][2], oa[mi][nj][3]);
        }
    }
}

// ================== causal flash attention on tensor cores (bf16 3-term) ==================
#define LDH_ 70
#define ATT_SMEM ((2*128 + 2*64 + 2*64) * LDH_ * 2)   /* 71680 bytes */

__global__ __launch_bounds__(256, 1) void attn_tc_kernel() {
    extern __shared__ char sm[];
    __nv_bfloat16* Qh = (__nv_bfloat16*)sm;            // [128][LDH_]
    __nv_bfloat16* Ql = Qh + 128 * LDH_;
    __nv_bfloat16* Kh = Ql + 128 * LDH_;               // [64][LDH_]
    __nv_bfloat16* Kl = Kh + 64 * LDH_;
    __nv_bfloat16* Vh = Kl + 64 * LDH_;                // [dh][tok]
    __nv_bfloat16* Vl = Vh + 64 * LDH_;

    const int qt = gridDim.x - 1 - blockIdx.x;         // largest-work CTAs first
    const int bhid = blockIdx.y;
    const int b = bhid >> 3, h = bhid & 7;
    const int q0 = qt * 128;
    const int tid = threadIdx.x, wid = tid >> 5, lane = tid & 31;
    const int g = lane >> 2, c01 = (lane & 3) * 2;
    const size_t rowbase = (size_t)(b * S_) * R_ + h * DH_;

    for (int i = tid; i < 128 * 16; i += 256) {
        const int row = i >> 4, seg = i & 15;
        float4 v = *(const float4*)(g_Q + rowbase + (size_t)(q0 + row) * R_ + seg * 4);
        float xv[4] = {v.x * 0.125f, v.y * 0.125f, v.z * 0.125f, v.w * 0.125f};
        #pragma unroll
        for (int c2 = 0; c2 < 4; c2 += 2) {
            uint32_t hi, lo;
            pack_hilo(xv[c2], xv[c2 + 1], hi, lo);
            *(uint32_t*)&Qh[row * LDH_ + seg * 4 + c2] = hi;
            *(uint32_t*)&Ql[row * LDH_ + seg * 4 + c2] = lo;
        }
    }

    float o[8][4] = {};
    float m0 = -1e30f, m1 = -1e30f, l0 = 0.f, l1 = 0.f;
    const int rowlo = q0 + wid * 16;
    const int r0g = rowlo + g;
    const int nkt = (q0 >> 6) + 2;

    float4 pk[4], pv[4];
    #pragma unroll
    for (int j = 0; j < 4; j++) {
        const int linear = tid + j * 256;
        const int row = linear >> 4, seg = linear & 15;
        pk[j] = *(const float4*)(g_K + rowbase + (size_t)row * R_ + seg * 4);
        pv[j] = *(const float4*)(g_V + rowbase + (size_t)row * R_ + seg * 4);
    }

    for (int kt = 0; kt < nkt; kt++) {
        const int k0 = kt * 64;
        __syncthreads();
        #pragma unroll
        for (int j = 0; j < 4; j++) {
            const int linear = tid + j * 256;
            const int row = linear >> 4, seg = linear & 15;
            float kv[4] = {pk[j].x, pk[j].y, pk[j].z, pk[j].w};
            float vv[4] = {pv[j].x, pv[j].y, pv[j].z, pv[j].w};
            #pragma unroll
            for (int c2 = 0; c2 < 4; c2 += 2) {
                uint32_t hi, lo;
                pack_hilo(kv[c2], kv[c2 + 1], hi, lo);
                *(uint32_t*)&Kh[row * LDH_ + seg * 4 + c2] = hi;
                *(uint32_t*)&Kl[row * LDH_ + seg * 4 + c2] = lo;
            }
            #pragma unroll
            for (int c = 0; c < 4; c++) {
                const int dh = seg * 4 + c;
                __nv_bfloat16 vh = __float2bfloat16(vv[c]);
                Vh[dh * LDH_ + row] = vh;
                Vl[dh * LDH_ + row] = __float2bfloat16(vv[c] - __bfloat162float(vh));
            }
        }
        __syncthreads();
        if (kt + 1 < nkt) {
            const int kn = k0 + 64;
            #pragma unroll
            for (int j = 0; j < 4; j++) {
                const int linear = tid + j * 256;
                const int row = linear >> 4, seg = linear & 15;
                pk[j] = *(const float4*)(g_K + rowbase + (size_t)(kn + row) * R_ + seg * 4);
                pv[j] = *(const float4*)(g_V + rowbase + (size_t)(kn + row) * R_ + seg * 4);
            }
        }

        if (k0 <= rowlo + 15) {
            float s[8][4] = {};
            #pragma unroll
            for (int kc = 0; kc < 4; kc++) {
                const int kk = kc * 16 + c01;
                const int ra = wid * 16 + g;
                uint32_t aH[4], aL[4];
                aH[0] = *(const uint32_t*)&Qh[ra * LDH_ + kk];
                aH[1] = *(const uint32_t*)&Qh[(ra + 8) * LDH_ + kk];
                aH[2] = *(const uint32_t*)&Qh[ra * LDH_ + kk + 8];
                aH[3] = *(const uint32_t*)&Qh[(ra + 8) * LDH_ + kk + 8];
                aL[0] = *(const uint32_t*)&Ql[ra * LDH_ + kk];
                aL[1] = *(const uint32_t*)&Ql[(ra + 8) * LDH_ + kk];
                aL[2] = *(const uint32_t*)&Ql[ra * LDH_ + kk + 8];
                aL[3] = *(const uint32_t*)&Ql[(ra + 8) * LDH_ + kk + 8];
                #pragma unroll
                for (int nj = 0; nj < 8; nj++) {
                    const int rn = nj * 8 + g;
                    uint32_t bH[2] = {*(const uint32_t*)&Kh[rn * LDH_ + kk],
                                      *(const uint32_t*)&Kh[rn * LDH_ + kk + 8]};
                    uint32_t bL[2] = {*(const uint32_t*)&Kl[rn * LDH_ + kk],
                                      *(const uint32_t*)&Kl[rn * LDH_ + kk + 8]};
                    mma16816(s[nj], aH, bH);
                    mma16816(s[nj], aH, bL);
                    mma16816(s[nj], aL, bH);
                }
            }
            if (k0 + 63 > rowlo) {
                #pragma unroll
                for (int nj = 0; nj < 8; nj++) {
                    const int tok = k0 + nj * 8 + c01;
                    if (tok > r0g)         s[nj][0] = -1e30f;
                    if (tok + 1 > r0g)     s[nj][1] = -1e30f;
                    if (tok > r0g + 8)     s[nj][2] = -1e30f;
                    if (tok + 1 > r0g + 8) s[nj][3] = -1e30f;
                }
            }
            float rm0 = -1e30f, rm1 = -1e30f;
            #pragma unroll
            for (int nj = 0; nj < 8; nj++) {
                rm0 = fmaxf(rm0, fmaxf(s[nj][0], s[nj][1]));
                rm1 = fmaxf(rm1, fmaxf(s[nj][2], s[nj][3]));
            }
            rm0 = fmaxf(rm0, __shfl_xor_sync(0xffffffffu, rm0, 1));
            rm0 = fmaxf(rm0, __shfl_xor_sync(0xffffffffu, rm0, 2));
            rm1 = fmaxf(rm1, __shfl_xor_sync(0xffffffffu, rm1, 1));
            rm1 = fmaxf(rm1, __shfl_xor_sync(0xffffffffu, rm1, 2));
            const float nm0 = fmaxf(m0, rm0), nm1 = fmaxf(m1, rm1);
            const float sc0 = __expf(m0 - nm0), sc1 = __expf(m1 - nm1);
            m0 = nm0; m1 = nm1;
            float rs0 = 0.f, rs1 = 0.f;
            #pragma unroll
            for (int nj = 0; nj < 8; nj++) {
                s[nj][0] = __expf(s[nj][0] - nm0);
                s[nj][1] = __expf(s[nj][1] - nm0);
                s[nj][2] = __expf(s[nj][2] - nm1);
                s[nj][3] = __expf(s[nj][3] - nm1);
                rs0 += s[nj][0] + s[nj][1];
                rs1 += s[nj][2] + s[nj][3];
            }
            rs0 += __shfl_xor_sync(0xffffffffu, rs0, 1);
            rs0 += __shfl_xor_sync(0xffffffffu, rs0, 2);
            rs1 += __shfl_xor_sync(0xffffffffu, rs1, 1);
            rs1 += __shfl_xor_sync(0xffffffffu, rs1, 2);
            l0 = l0 * sc0 + rs0;
            l1 = l1 * sc1 + rs1;
            #pragma unroll
            for (int nj = 0; nj < 8; nj++) {
                o[nj][0] *= sc0; o[nj][1] *= sc0;
                o[nj][2] *= sc1; o[nj][3] *= sc1;
            }
            #pragma unroll
            for (int kc = 0; kc < 4; kc++) {
                uint32_t aH[4], aL[4];
                pack_hilo(s[2 * kc][0],     s[2 * kc][1],     aH[0], aL[0]);
                pack_hilo(s[2 * kc][2],     s[2 * kc][3],     aH[1], aL[1]);
                pack_hilo(s[2 * kc + 1][0], s[2 * kc + 1][1], aH[2], aL[2]);
                pack_hilo(s[2 * kc + 1][2], s[2 * kc + 1][3], aH[3], aL[3]);
                const int kk = kc * 16 + c01;
                #pragma unroll
                for (int nj = 0; nj < 8; nj++) {
                    const int rn = nj * 8 + g;
                    uint32_t bH[2] = {*(const uint32_t*)&Vh[rn * LDH_ + kk],
                                      *(const uint32_t*)&Vh[rn * LDH_ + kk + 8]};
                    uint32_t bL[2] = {*(const uint32_t*)&Vl[rn * LDH_ + kk],
                                      *(const uint32_t*)&Vl[rn * LDH_ + kk + 8]};
                    mma16816(o[nj], aH, bH);
                    mma16816(o[nj], aH, bL);
                    mma16816(o[nj], aL, bH);
                }
            }
        }
    }
    // ---- epilogue: write tf32-rounded AO (consumed by tf32 expand + router_o) ----
    const float inv0 = 1.f / l0, inv1 = 1.f / l1;
    #pragma unroll
    for (int nj = 0; nj < 8; nj++) {
        const int cc = h * DH_ + nj * 8 + c01;
        *(float2*)&g_AO[(size_t)(b * S_ + r0g) * R_ + cc] =
            make_float2(tf32r(o[nj][0] * inv0), tf32r(o[nj][1] * inv0));
        *(float2*)&g_AO[(size_t)(b * S_ + r0g + 8) * R_ + cc] =
            make_float2(tf32r(o[nj][2] * inv1), tf32r(o[nj][3] * inv1));
    }
}

// ================== output router ==================
__global__ void router_o_kernel(const float* __restrict__ wo) {
    __shared__ float as[R_];
    __shared__ float logits[NE_];
    const int t = blockIdx.x;
    for (int i = threadIdx.x; i < R_; i += 256) as[i] = g_AO[(size_t)t * R_ + i];
    __syncthreads();
    const int warp = threadIdx.x >> 5, lane = threadIdx.x & 31;
    const float* w = wo + warp * R_;
    float s = 0.f;
    for (int r = lane; r < R_; r += 32) s += as[r] * w[r];
    #pragma unroll
    for (int o = 16; o > 0; o >>= 1) s += __shfl_xor_sync(0xffffffffu, s, o);
    if (lane == 0) logits[warp] = s;
    __syncthreads();
    if (threadIdx.x == 0) {
        float m = -1e30f;
        for (int n = 0; n < NE_; n++) m = fmaxf(m, logits[n]);
        float e[NE_], sum = 0.f;
        for (int n = 0; n < NE_; n++) { e[n] = expf(logits[n] - m); sum += e[n]; }
        const float inv = 1.f / sum;
        for (int n = 0; n < NE_; n++) g_WO[t][n] = e[n] * inv;
    }
}

// ================== launch ==================
extern "C" void kernel_launch(void* const* d_in, const int* in_sizes, int n_in,
                              void* d_out, int out_size) {
    const float* x  = (const float*)d_in[0];
    const float* cn = (const float*)d_in[2];
    const float* en = (const float*)d_in[3];
    const float* wq = (const float*)d_in[4];
    const float* wk = (const float*)d_in[5];
    const float* wv = (const float*)d_in[6];
    const float* wo = (const float*)d_in[7];
    float* out = (float*)d_out;

    cudaFuncSetAttribute((const void*)compress_mma_kernel,
                         cudaFuncAttributeMaxDynamicSharedMemorySize, MSMEM_TOTAL);
    cudaFuncSetAttribute((const void*)expand_mma_kernel,
                         cudaFuncAttributeMaxDynamicSharedMemorySize, ESMEM_TOTAL);
    cudaFuncSetAttribute((const void*)attn_tc_kernel,
                         cudaFuncAttributeMaxDynamicSharedMemorySize, ATT_SMEM);

    __nv_bfloat16 *xhi, *xlo, *cnthi, *cntlo;
    float* ent;
    cudaGetSymbolAddress((void**)&xhi, g_Xhi);
    cudaGetSymbolAddress((void**)&xlo, g_Xlo);
    cudaGetSymbolAddress((void**)&cnthi, g_CNThi);
    cudaGetSymbolAddress((void**)&cntlo, g_CNTlo);
    cudaGetSymbolAddress((void**)&ent, g_ENT);

    // prep
    split_bf16_kernel<<<(unsigned)((size_t)T_*D_/4/256), 256>>>(x, xhi, xlo, (size_t)T_*D_/4);
    transpose_split_kernel<<<dim3(R_/32, D_/32, NC_), dim3(32, 8)>>>(cn, cnthi, cntlo, D_, R_);
    transpose_tf32_kernel<<<dim3(D_/32, R_/32, NE_), dim3(32, 8)>>>(en, ent, R_, D_);
    router3_kernel<<<T_, 256>>>(x, wq, wk, wv);
    // main pipeline
    compress_mma_kernel<<<dim3(R_/64, T_/128), 256, MSMEM_TOTAL>>>();
    attn_tc_kernel<<<dim3(S_/128, B_*H_), 256, ATT_SMEM>>>();
    router_o_kernel<<<T_, 256>>>(wo);
    expand_mma_kernel<<<dim3(D_/64, T_/128), 256, ESMEM_TOTAL>>>(out);
}

// round 15
// speedup vs baseline: 4.2078x; 1.0892x over previous
#include <cuda_runtime.h>
#include <cuda_bf16.h>
#include <math.h>
#include <stdint.h>

#define B_  4
#define S_  2048
#define D_  1024
#define R_  512
#define H_  8
#define DH_ 64
#define NC_ 8
#define NE_ 8
#define T_  (B_*S_)   // 8192 tokens

// ================= helpers =================
__device__ __forceinline__ uint32_t smem_to_u32(const void* p) {
    uint32_t a;
    asm("{ .reg .u64 t; cvta.to.shared.u64 t, %1; cvt.u32.u64 %0, t; }" : "=r"(a) : "l"(p));
    return a;
}
__device__ __forceinline__ void cpa16(uint32_t dst, const void* src) {
    asm volatile("cp.async.cg.shared.global [%0], [%1], 16;" :: "r"(dst), "l"(src));
}
#define CP_COMMIT() asm volatile("cp.async.commit_group;" ::: "memory")
#define CP_WAIT0()  asm volatile("cp.async.wait_group 0;" ::: "memory")
#define CP_WAIT1()  asm volatile("cp.async.wait_group 1;" ::: "memory")

// m16n8k16 bf16 MMA, f32 accum, A row-major, B col-major
__device__ __forceinline__ void mma16816(float* c, const uint32_t* a, const uint32_t* b) {
    asm volatile("mma.sync.aligned.m16n8k16.row.col.f32.bf16.bf16.f32 "
        "{%0,%1,%2,%3}, {%4,%5,%6,%7}, {%8,%9}, {%0,%1,%2,%3};"
        : "+f"(c[0]), "+f"(c[1]), "+f"(c[2]), "+f"(c[3])
        : "r"(a[0]), "r"(a[1]), "r"(a[2]), "r"(a[3]), "r"(b[0]), "r"(b[1]));
}
// m16n8k8 tf32 MMA
__device__ __forceinline__ void mma16808(float* c, const uint32_t* a, const uint32_t* b) {
    asm volatile("mma.sync.aligned.m16n8k8.row.col.f32.tf32.tf32.f32 "
        "{%0,%1,%2,%3}, {%4,%5,%6,%7}, {%8,%9}, {%0,%1,%2,%3};"
        : "+f"(c[0]), "+f"(c[1]), "+f"(c[2]), "+f"(c[3])
        : "r"(a[0]), "r"(a[1]), "r"(a[2]), "r"(a[3]), "r"(b[0]), "r"(b[1]));
}
__device__ __forceinline__ float tf32r(float x) {
    uint32_t u;
    asm("cvt.rna.tf32.f32 %0, %1;" : "=r"(u) : "f"(x));
    return __uint_as_float(u);
}
// pack two floats into bf16x2 hi + residual lo
__device__ __forceinline__ void pack_hilo(float x, float y, uint32_t& hi, uint32_t& lo) {
    __nv_bfloat16 hx = __float2bfloat16(x), hy = __float2bfloat16(y);
    __nv_bfloat162 hv; hv.x = hx; hv.y = hy;
    hi = *(uint32_t*)&hv;
    __nv_bfloat162 lv;
    lv.x = __float2bfloat16(x - __bfloat162float(hx));
    lv.y = __float2bfloat16(y - __bfloat162float(hy));
    lo = *(uint32_t*)&lv;
}

// ---------------- scratch (no allocations allowed) ----------------
__device__ float g_W3[3][T_][NC_];
__device__ float g_Q[(size_t)T_*R_];
__device__ float g_K[(size_t)T_*R_];
__device__ float g_V[(size_t)T_*R_];
__device__ float g_AO[(size_t)T_*R_];      // tf32-rounded by attn epilogue
__device__ float g_WO[T_][NE_];
__device__ float g_X32[(size_t)T_*D_];     // tf32-rounded x
__device__ float g_CNT32[(size_t)NC_*R_*D_]; // [n][r][d], tf32-rounded
__device__ float g_ENT[(size_t)NE_*D_*R_];   // [n][d][r], tf32-rounded

// ================= prep: fp32 -> tf32-rounded fp32 (elementwise) =================
__global__ void round_tf32_kernel(const float* __restrict__ in,
                                  float* __restrict__ o32, size_t n4) {
    size_t i = (size_t)blockIdx.x * blockDim.x + threadIdx.x;
    if (i >= n4) return;
    float4 x = ((const float4*)in)[i];
    x.x = tf32r(x.x); x.y = tf32r(x.y); x.z = tf32r(x.z); x.w = tf32r(x.w);
    ((float4*)o32)[i] = x;
}

// ===== prep: transpose [n][DIN][DOUT] fp32 -> [n][DOUT][DIN] tf32-rounded fp32 =====
__global__ void transpose_tf32_kernel(const float* __restrict__ in,
                                      float* __restrict__ o32,
                                      int DIN, int DOUT) {
    __shared__ float ts[32][33];
    const int n = blockIdx.z;
    const float* src = in + (size_t)n * DIN * DOUT;
    const int r0 = blockIdx.x * 32, d0 = blockIdx.y * 32;
    for (int k = threadIdx.y; k < 32; k += 8)
        ts[k][threadIdx.x] = src[(size_t)(d0 + k) * DOUT + r0 + threadIdx.x];
    __syncthreads();
    const size_t obase = (size_t)n * DIN * DOUT;
    for (int k = threadIdx.y; k < 32; k += 8) {
        float v = ts[threadIdx.x][k];
        size_t o = obase + (size_t)(r0 + k) * DIN + d0 + threadIdx.x;
        o32[o] = tf32r(v);
    }
}

// ================== router q/k/v (float4 vectorized) ==================
__global__ void router3_kernel(const float* __restrict__ x,
                               const float* __restrict__ wq,
                               const float* __restrict__ wk,
                               const float* __restrict__ wv) {
    __shared__ float4 xs4[D_/4];
    __shared__ float logits[3][NC_];
    const int t = blockIdx.x;
    const float4* xr = (const float4*)(x + (size_t)t * D_);
    for (int i = threadIdx.x; i < D_/4; i += 256) xs4[i] = xr[i];
    __syncthreads();
    const int warp = threadIdx.x >> 5, lane = threadIdx.x & 31;
    const float* wr[3] = {wq, wk, wv};
    for (int rt = 0; rt < 3; rt++) {
        const float4* w4 = (const float4*)(wr[rt] + warp * D_);
        float s = 0.f;
        #pragma unroll
        for (int d = lane; d < D_/4; d += 32) {
            const float4 a = xs4[d], b = w4[d];
            s += a.x*b.x + a.y*b.y + a.z*b.z + a.w*b.w;
        }
        #pragma unroll
        for (int o = 16; o > 0; o >>= 1) s += __shfl_xor_sync(0xffffffffu, s, o);
        if (lane == 0) logits[rt][warp] = s;
    }
    __syncthreads();
    if (threadIdx.x < 3) {
        const int rt = threadIdx.x;
        float m = -1e30f;
        for (int n = 0; n < NC_; n++) m = fmaxf(m, logits[rt][n]);
        float e[NC_], sum = 0.f;
        for (int n = 0; n < NC_; n++) { e[n] = expf(logits[rt][n] - m); sum += e[n]; }
        const float inv = 1.f / sum;
        for (int n = 0; n < NC_; n++) g_W3[rt][t][n] = e[n] * inv;
    }
}

// ============== SMEM layout for the tf32 GEMMs (fp32, stride 132 floats) ==============
#define LDE_ 132
#define EOFF_WS 0
#define EOFF_A  16384
#define EOFF_B0 (EOFF_A + 128*LDE_*4)
#define EOFF_B1 (EOFF_B0 + 64*LDE_*4)
#define ESMEM_TOTAL (EOFF_B1 + 64*LDE_*4)   /* 151552 */

__device__ __forceinline__ void load_Af32(uint32_t sb, const float* A, size_t rowstride,
                                          int t0, int kbase, int tid) {
    for (int i = tid; i < 128 * 32; i += 256) {
        const int row = i >> 5, seg = i & 31;
        const uint32_t doff = (uint32_t)(row * LDE_ + seg * 4) * 4;
        const size_t soff = (size_t)(t0 + row) * rowstride + kbase + seg * 4;
        cpa16(sb + EOFF_A + doff, A + soff);
    }
}
__device__ __forceinline__ void load_Bf32(uint32_t sb, const float* Bsrc, size_t rowstride,
                                          size_t rbase, int kbase, int bb, int tid) {
    const uint32_t ob = bb ? EOFF_B1 : EOFF_B0;
    for (int i = tid; i < 64 * 32; i += 256) {
        const int row = i >> 5, seg = i & 31;
        const uint32_t doff = (uint32_t)(row * LDE_ + seg * 4) * 4;
        const size_t soff = (rbase + row) * rowstride + kbase + seg * 4;
        cpa16(sb + ob + doff, Bsrc + soff);
    }
}

// one superchunk of tf32 MMAs: part += A(128xK128) B(64xK128)^T for this warp tile
__device__ __forceinline__ void tf32_chunk(const uint32_t* As, const uint32_t* Bs,
                                           int wm, int wn, int g, int c4,
                                           float part[2][4][4]) {
    #pragma unroll
    for (int ks = 0; ks < 16; ks++) {
        const int k8 = ks * 8;
        uint32_t a[2][4];
        #pragma unroll
        for (int mi = 0; mi < 2; mi++) {
            const int r = wm * 32 + mi * 16 + g;
            a[mi][0] = As[r * LDE_ + k8 + c4];
            a[mi][1] = As[(r + 8) * LDE_ + k8 + c4];
            a[mi][2] = As[r * LDE_ + k8 + c4 + 4];
            a[mi][3] = As[(r + 8) * LDE_ + k8 + c4 + 4];
        }
        uint32_t b[4][2];
        #pragma unroll
        for (int nj = 0; nj < 4; nj++) {
            const int rn = wn * 32 + nj * 8 + g;
            b[nj][0] = Bs[rn * LDE_ + k8 + c4];
            b[nj][1] = Bs[rn * LDE_ + k8 + c4 + 4];
        }
        #pragma unroll
        for (int mi = 0; mi < 2; mi++)
            #pragma unroll
            for (int nj = 0; nj < 4; nj++)
                mma16808(part[mi][nj], a[mi], b[nj]);
    }
}

// ================== compress via tf32 mma (single pass) ==================
__global__ __launch_bounds__(256, 1) void compress_mma_kernel() {
    extern __shared__ char smem[];
    const uint32_t sb = smem_to_u32(smem);
    const int tid = threadIdx.x, wid = tid >> 5, lane = tid & 31;
    const int wm = wid & 3, wn = wid >> 2;
    const int g = lane >> 2, c4 = lane & 3, k04 = c4 * 2;
    const int c0 = blockIdx.x * 64;      // r tile
    const int t0 = blockIdx.y * 128;     // token tile

    float* wsf = (float*)(smem + EOFF_WS);   // Ws[rt][n][row], 12KB
    for (int i = tid; i < 3 * NC_ * 128; i += 256) {
        const int rt = i >> 10, n = (i >> 7) & 7, row = i & 127;
        wsf[i] = g_W3[rt][t0 + row][n];
    }

    const int NIT = 8 * NC_;  // 8 superchunks (K=1024) x 8 neurons
    load_Af32(sb, g_X32, D_, t0, 0, tid);
    load_Bf32(sb, g_CNT32, D_, (size_t)0 * R_ + c0, 0, 0, tid);
    CP_COMMIT();
    load_Bf32(sb, g_CNT32, D_, (size_t)1 * R_ + c0, 0, 1, tid);
    CP_COMMIT();

    float qa[2][4][4] = {}, ka[2][4][4] = {}, va[2][4][4] = {};
    const uint32_t* As = (const uint32_t*)(smem + EOFF_A);

    for (int it = 0; it < NIT; it++) {
        const int sc = it >> 3, n = it & 7, bb = it & 1;
        if (it != 0 && (it & 7) == 0) { CP_WAIT0(); } else { CP_WAIT1(); }
        __syncthreads();

        const uint32_t* Bs = (const uint32_t*)(smem + (bb ? EOFF_B1 : EOFF_B0));
        float part[2][4][4] = {};
        tf32_chunk(As, Bs, wm, wn, g, c4, part);

        #pragma unroll
        for (int mi = 0; mi < 2; mi++) {
            const int r0 = wm * 32 + mi * 16 + g;
            const float wq0 = wsf[0 * 1024 + n * 128 + r0], wq1 = wsf[0 * 1024 + n * 128 + r0 + 8];
            const float wk0 = wsf[1 * 1024 + n * 128 + r0], wk1 = wsf[1 * 1024 + n * 128 + r0 + 8];
            const float wv0 = wsf[2 * 1024 + n * 128 + r0], wv1 = wsf[2 * 1024 + n * 128 + r0 + 8];
            #pragma unroll
            for (int nj = 0; nj < 4; nj++) {
                qa[mi][nj][0] += wq0 * part[mi][nj][0]; qa[mi][nj][1] += wq0 * part[mi][nj][1];
                qa[mi][nj][2] += wq1 * part[mi][nj][2]; qa[mi][nj][3] += wq1 * part[mi][nj][3];
                ka[mi][nj][0] += wk0 * part[mi][nj][0]; ka[mi][nj][1] += wk0 * part[mi][nj][1];
                ka[mi][nj][2] += wk1 * part[mi][nj][2]; ka[mi][nj][3] += wk1 * part[mi][nj][3];
                va[mi][nj][0] += wv0 * part[mi][nj][0]; va[mi][nj][1] += wv0 * part[mi][nj][1];
                va[mi][nj][2] += wv1 * part[mi][nj][2]; va[mi][nj][3] += wv1 * part[mi][nj][3];
            }
        }
        __syncthreads();

        if (it + 1 < NIT) {
            if (((it + 1) & 7) == 0)
                load_Af32(sb, g_X32, D_, t0, (sc + 1) * 128, tid);
            if (it + 2 < NIT) {
                const int sc2 = (it + 2) >> 3, n2 = (it + 2) & 7;
                load_Bf32(sb, g_CNT32, D_, (size_t)n2 * R_ + c0, sc2 * 128, (it + 2) & 1, tid);
            }
            CP_COMMIT();
        }
    }

    #pragma unroll
    for (int mi = 0; mi < 2; mi++) {
        const int r0 = t0 + wm * 32 + mi * 16 + g;
        #pragma unroll
        for (int nj = 0; nj < 4; nj++) {
            const int cc = c0 + wn * 32 + nj * 8 + k04;
            *(float2*)&g_Q[(size_t)r0 * R_ + cc]       = make_float2(qa[mi][nj][0], qa[mi][nj][1]);
            *(float2*)&g_Q[(size_t)(r0 + 8) * R_ + cc] = make_float2(qa[mi][nj][2], qa[mi][nj][3]);
            *(float2*)&g_K[(size_t)r0 * R_ + cc]       = make_float2(ka[mi][nj][0], ka[mi][nj][1]);
            *(float2*)&g_K[(size_t)(r0 + 8) * R_ + cc] = make_float2(ka[mi][nj][2], ka[mi][nj][3]);
            *(float2*)&g_V[(size_t)r0 * R_ + cc]       = make_float2(va[mi][nj][0], va[mi][nj][1]);
            *(float2*)&g_V[(size_t)(r0 + 8) * R_ + cc] = make_float2(va[mi][nj][2], va[mi][nj][3]);
        }
    }
}

// ============== expand via tf32 mma (single pass, pre-rounded operands) ==============
__global__ __launch_bounds__(256, 1) void expand_mma_kernel(float* __restrict__ out) {
    extern __shared__ char smem[];
    const uint32_t sb = smem_to_u32(smem);
    const int tid = threadIdx.x, wid = tid >> 5, lane = tid & 31;
    const int wm = wid & 3, wn = wid >> 2;
    const int g = lane >> 2, c4 = lane & 3, k04 = c4 * 2;
    const int c0 = blockIdx.x * 64;      // d tile
    const int t0 = blockIdx.y * 128;     // token tile

    float* wsf = (float*)(smem + EOFF_WS);
    for (int i = tid; i < NE_ * 128; i += 256) {
        const int n = i >> 7, row = i & 127;
        wsf[i] = g_WO[t0 + row][n];
    }

    const int NIT = 4 * NE_;  // 4 superchunks (K=512) x 8 neurons
    load_Af32(sb, g_AO, R_, t0, 0, tid);
    load_Bf32(sb, g_ENT, R_, (size_t)0 * D_ + c0, 0, 0, tid);
    CP_COMMIT();
    load_Bf32(sb, g_ENT, R_, (size_t)1 * D_ + c0, 0, 1, tid);
    CP_COMMIT();

    float oa[2][4][4] = {};
    const uint32_t* As = (const uint32_t*)(smem + EOFF_A);

    for (int it = 0; it < NIT; it++) {
        const int sc = it >> 3, n = it & 7, bb = it & 1;
        if (it != 0 && (it & 7) == 0) { CP_WAIT0(); } else { CP_WAIT1(); }
        __syncthreads();

        const uint32_t* Bs = (const uint32_t*)(smem + (bb ? EOFF_B1 : EOFF_B0));
        float part[2][4][4] = {};
        tf32_chunk(As, Bs, wm, wn, g, c4, part);

        #pragma unroll
        for (int mi = 0; mi < 2; mi++) {
            const int r0 = wm * 32 + mi * 16 + g;
            const float w0 = wsf[n * 128 + r0], w1 = wsf[n * 128 + r0 + 8];
            #pragma unroll
            for (int nj = 0; nj < 4; nj++) {
                oa[mi][nj][0] += w0 * part[mi][nj][0]; oa[mi][nj][1] += w0 * part[mi][nj][1];
                oa[mi][nj][2] += w1 * part[mi][nj][2]; oa[mi][nj][3] += w1 * part[mi][nj][3];
            }
        }
        __syncthreads();

        if (it + 1 < NIT) {
            if (((it + 1) & 7) == 0)
                load_Af32(sb, g_AO, R_, t0, (sc + 1) * 128, tid);
            if (it + 2 < NIT) {
                const int sc2 = (it + 2) >> 3, n2 = (it + 2) & 7;
                load_Bf32(sb, g_ENT, R_, (size_t)n2 * D_ + c0, sc2 * 128, (it + 2) & 1, tid);
            }
            CP_COMMIT();
        }
    }

    #pragma unroll
    for (int mi = 0; mi < 2; mi++) {
        const int r0 = t0 + wm * 32 + mi * 16 + g;
        #pragma unroll
        for (int nj = 0; nj < 4; nj++) {
            const int cc = c0 + wn * 32 + nj * 8 + k04;
            *(float2*)&out[(size_t)r0 * D_ + cc]       = make_float2(oa[mi][nj][0], oa[mi][nj][1]);
            *(float2*)&out[(size_t)(r0 + 8) * D_ + cc] = make_float2(oa[mi][nj][2], oa[mi][nj][3]);
        }
    }
}

// ================== causal flash attention on tensor cores (bf16 3-term) ==================
#define LDH_ 70
#define ATT_SMEM ((2*128 + 2*64 + 2*64) * LDH_ * 2)   /* 71680 bytes */

__global__ __launch_bounds__(256, 1) void attn_tc_kernel() {
    extern __shared__ char sm[];
    __nv_bfloat16* Qh = (__nv_bfloat16*)sm;            // [128][LDH_]
    __nv_bfloat16* Ql = Qh + 128 * LDH_;
    __nv_bfloat16* Kh = Ql + 128 * LDH_;               // [64][LDH_]
    __nv_bfloat16* Kl = Kh + 64 * LDH_;
    __nv_bfloat16* Vh = Kl + 64 * LDH_;                // [dh][tok]
    __nv_bfloat16* Vl = Vh + 64 * LDH_;

    const int qt = gridDim.x - 1 - blockIdx.x;         // largest-work CTAs first
    const int bhid = blockIdx.y;
    const int b = bhid >> 3, h = bhid & 7;
    const int q0 = qt * 128;
    const int tid = threadIdx.x, wid = tid >> 5, lane = tid & 31;
    const int g = lane >> 2, c01 = (lane & 3) * 2;
    const size_t rowbase = (size_t)(b * S_) * R_ + h * DH_;

    for (int i = tid; i < 128 * 16; i += 256) {
        const int row = i >> 4, seg = i & 15;
        float4 v = *(const float4*)(g_Q + rowbase + (size_t)(q0 + row) * R_ + seg * 4);
        float xv[4] = {v.x * 0.125f, v.y * 0.125f, v.z * 0.125f, v.w * 0.125f};
        #pragma unroll
        for (int c2 = 0; c2 < 4; c2 += 2) {
            uint32_t hi, lo;
            pack_hilo(xv[c2], xv[c2 + 1], hi, lo);
            *(uint32_t*)&Qh[row * LDH_ + seg * 4 + c2] = hi;
            *(uint32_t*)&Ql[row * LDH_ + seg * 4 + c2] = lo;
        }
    }

    float o[8][4] = {};
    float m0 = -1e30f, m1 = -1e30f, l0 = 0.f, l1 = 0.f;
    const int rowlo = q0 + wid * 16;
    const int r0g = rowlo + g;
    const int nkt = (q0 >> 6) + 2;

    float4 pk[4], pv[4];
    #pragma unroll
    for (int j = 0; j < 4; j++) {
        const int linear = tid + j * 256;
        const int row = linear >> 4, seg = linear & 15;
        pk[j] = *(const float4*)(g_K + rowbase + (size_t)row * R_ + seg * 4);
        pv[j] = *(const float4*)(g_V + rowbase + (size_t)row * R_ + seg * 4);
    }

    for (int kt = 0; kt < nkt; kt++) {
        const int k0 = kt * 64;
        __syncthreads();
        #pragma unroll
        for (int j = 0; j < 4; j++) {
            const int linear = tid + j * 256;
            const int row = linear >> 4, seg = linear & 15;
            float kv[4] = {pk[j].x, pk[j].y, pk[j].z, pk[j].w};
            float vv[4] = {pv[j].x, pv[j].y, pv[j].z, pv[j].w};
            #pragma unroll
            for (int c2 = 0; c2 < 4; c2 += 2) {
                uint32_t hi, lo;
                pack_hilo(kv[c2], kv[c2 + 1], hi, lo);
                *(uint32_t*)&Kh[row * LDH_ + seg * 4 + c2] = hi;
                *(uint32_t*)&Kl[row * LDH_ + seg * 4 + c2] = lo;
            }
            #pragma unroll
            for (int c = 0; c < 4; c++) {
                const int dh = seg * 4 + c;
                __nv_bfloat16 vh = __float2bfloat16(vv[c]);
                Vh[dh * LDH_ + row] = vh;
                Vl[dh * LDH_ + row] = __float2bfloat16(vv[c] - __bfloat162float(vh));
            }
        }
        __syncthreads();
        if (kt + 1 < nkt) {
            const int kn = k0 + 64;
            #pragma unroll
            for (int j = 0; j < 4; j++) {
                const int linear = tid + j * 256;
                const int row = linear >> 4, seg = linear & 15;
                pk[j] = *(const float4*)(g_K + rowbase + (size_t)(kn + row) * R_ + seg * 4);
                pv[j] = *(const float4*)(g_V + rowbase + (size_t)(kn + row) * R_ + seg * 4);
            }
        }

        if (k0 <= rowlo + 15) {
            float s[8][4] = {};
            #pragma unroll
            for (int kc = 0; kc < 4; kc++) {
                const int kk = kc * 16 + c01;
                const int ra = wid * 16 + g;
                uint32_t aH[4], aL[4];
                aH[0] = *(const uint32_t*)&Qh[ra * LDH_ + kk];
                aH[1] = *(const uint32_t*)&Qh[(ra + 8) * LDH_ + kk];
                aH[2] = *(const uint32_t*)&Qh[ra * LDH_ + kk + 8];
                aH[3] = *(const uint32_t*)&Qh[(ra + 8) * LDH_ + kk + 8];
                aL[0] = *(const uint32_t*)&Ql[ra * LDH_ + kk];
                aL[1] = *(const uint32_t*)&Ql[(ra + 8) * LDH_ + kk];
                aL[2] = *(const uint32_t*)&Ql[ra * LDH_ + kk + 8];
                aL[3] = *(const uint32_t*)&Ql[(ra + 8) * LDH_ + kk + 8];
                #pragma unroll
                for (int nj = 0; nj < 8; nj++) {
                    const int rn = nj * 8 + g;
                    uint32_t bH[2] = {*(const uint32_t*)&Kh[rn * LDH_ + kk],
                                      *(const uint32_t*)&Kh[rn * LDH_ + kk + 8]};
                    uint32_t bL[2] = {*(const uint32_t*)&Kl[rn * LDH_ + kk],
                                      *(const uint32_t*)&Kl[rn * LDH_ + kk + 8]};
                    mma16816(s[nj], aH, bH);
                    mma16816(s[nj], aH, bL);
                    mma16816(s[nj], aL, bH);
                }
            }
            if (k0 + 63 > rowlo) {
                #pragma unroll
                for (int nj = 0; nj < 8; nj++) {
                    const int tok = k0 + nj * 8 + c01;
                    if (tok > r0g)         s[nj][0] = -1e30f;
                    if (tok + 1 > r0g)     s[nj][1] = -1e30f;
                    if (tok > r0g + 8)     s[nj][2] = -1e30f;
                    if (tok + 1 > r0g + 8) s[nj][3] = -1e30f;
                }
            }
            float rm0 = -1e30f, rm1 = -1e30f;
            #pragma unroll
            for (int nj = 0; nj < 8; nj++) {
                rm0 = fmaxf(rm0, fmaxf(s[nj][0], s[nj][1]));
                rm1 = fmaxf(rm1, fmaxf(s[nj][2], s[nj][3]));
            }
            rm0 = fmaxf(rm0, __shfl_xor_sync(0xffffffffu, rm0, 1));
            rm0 = fmaxf(rm0, __shfl_xor_sync(0xffffffffu, rm0, 2));
            rm1 = fmaxf(rm1, __shfl_xor_sync(0xffffffffu, rm1, 1));
            rm1 = fmaxf(rm1, __shfl_xor_sync(0xffffffffu, rm1, 2));
            const float nm0 = fmaxf(m0, rm0), nm1 = fmaxf(m1, rm1);
            const float sc0 = __expf(m0 - nm0), sc1 = __expf(m1 - nm1);
            m0 = nm0; m1 = nm1;
            float rs0 = 0.f, rs1 = 0.f;
            #pragma unroll
            for (int nj = 0; nj < 8; nj++) {
                s[nj][0] = __expf(s[nj][0] - nm0);
                s[nj][1] = __expf(s[nj][1] - nm0);
                s[nj][2] = __expf(s[nj][2] - nm1);
                s[nj][3] = __expf(s[nj][3] - nm1);
                rs0 += s[nj][0] + s[nj][1];
                rs1 += s[nj][2] + s[nj][3];
            }
            rs0 += __shfl_xor_sync(0xffffffffu, rs0, 1);
            rs0 += __shfl_xor_sync(0xffffffffu, rs0, 2);
            rs1 += __shfl_xor_sync(0xffffffffu, rs1, 1);
            rs1 += __shfl_xor_sync(0xffffffffu, rs1, 2);
            l0 = l0 * sc0 + rs0;
            l1 = l1 * sc1 + rs1;
            #pragma unroll
            for (int nj = 0; nj < 8; nj++) {
                o[nj][0] *= sc0; o[nj][1] *= sc0;
                o[nj][2] *= sc1; o[nj][3] *= sc1;
            }
            #pragma unroll
            for (int kc = 0; kc < 4; kc++) {
                uint32_t aH[4], aL[4];
                pack_hilo(s[2 * kc][0],     s[2 * kc][1],     aH[0], aL[0]);
                pack_hilo(s[2 * kc][2],     s[2 * kc][3],     aH[1], aL[1]);
                pack_hilo(s[2 * kc + 1][0], s[2 * kc + 1][1], aH[2], aL[2]);
                pack_hilo(s[2 * kc + 1][2], s[2 * kc + 1][3], aH[3], aL[3]);
                const int kk = kc * 16 + c01;
                #pragma unroll
                for (int nj = 0; nj < 8; nj++) {
                    const int rn = nj * 8 + g;
                    uint32_t bH[2] = {*(const uint32_t*)&Vh[rn * LDH_ + kk],
                                      *(const uint32_t*)&Vh[rn * LDH_ + kk + 8]};
                    uint32_t bL[2] = {*(const uint32_t*)&Vl[rn * LDH_ + kk],
                                      *(const uint32_t*)&Vl[rn * LDH_ + kk + 8]};
                    mma16816(o[nj], aH, bH);
                    mma16816(o[nj], aH, bL);
                    mma16816(o[nj], aL, bH);
                }
            }
        }
    }
    // ---- epilogue: write tf32-rounded AO (consumed by tf32 expand + router_o) ----
    const float inv0 = 1.f / l0, inv1 = 1.f / l1;
    #pragma unroll
    for (int nj = 0; nj < 8; nj++) {
        const int cc = h * DH_ + nj * 8 + c01;
        *(float2*)&g_AO[(size_t)(b * S_ + r0g) * R_ + cc] =
            make_float2(tf32r(o[nj][0] * inv0), tf32r(o[nj][1] * inv0));
        *(float2*)&g_AO[(size_t)(b * S_ + r0g + 8) * R_ + cc] =
            make_float2(tf32r(o[nj][2] * inv1), tf32r(o[nj][3] * inv1));
    }
}

// ================== output router ==================
__global__ void router_o_kernel(const float* __restrict__ wo) {
    __shared__ float as[R_];
    __shared__ float logits[NE_];
    const int t = blockIdx.x;
    for (int i = threadIdx.x; i < R_; i += 256) as[i] = g_AO[(size_t)t * R_ + i];
    __syncthreads();
    const int warp = threadIdx.x >> 5, lane = threadIdx.x & 31;
    const float* w = wo + warp * R_;
    float s = 0.f;
    for (int r = lane; r < R_; r += 32) s += as[r] * w[r];
    #pragma unroll
    for (int o = 16; o > 0; o >>= 1) s += __shfl_xor_sync(0xffffffffu, s, o);
    if (lane == 0) logits[warp] = s;
    __syncthreads();
    if (threadIdx.x == 0) {
        float m = -1e30f;
        for (int n = 0; n < NE_; n++) m = fmaxf(m, logits[n]);
        float e[NE_], sum = 0.f;
        for (int n = 0; n < NE_; n++) { e[n] = expf(logits[n] - m); sum += e[n]; }
        const float inv = 1.f / sum;
        for (int n = 0; n < NE_; n++) g_WO[t][n] = e[n] * inv;
    }
}

// ================== launch ==================
extern "C" void kernel_launch(void* const* d_in, const int* in_sizes, int n_in,
                              void* d_out, int out_size) {
    const float* x  = (const float*)d_in[0];
    const float* cn = (const float*)d_in[2];
    const float* en = (const float*)d_in[3];
    const float* wq = (const float*)d_in[4];
    const float* wk = (const float*)d_in[5];
    const float* wv = (const float*)d_in[6];
    const float* wo = (const float*)d_in[7];
    float* out = (float*)d_out;

    cudaFuncSetAttribute((const void*)compress_mma_kernel,
                         cudaFuncAttributeMaxDynamicSharedMemorySize, ESMEM_TOTAL);
    cudaFuncSetAttribute((const void*)expand_mma_kernel,
                         cudaFuncAttributeMaxDynamicSharedMemorySize, ESMEM_TOTAL);
    cudaFuncSetAttribute((const void*)attn_tc_kernel,
                         cudaFuncAttributeMaxDynamicSharedMemorySize, ATT_SMEM);

    float *x32, *cnt32, *ent;
    cudaGetSymbolAddress((void**)&x32, g_X32);
    cudaGetSymbolAddress((void**)&cnt32, g_CNT32);
    cudaGetSymbolAddress((void**)&ent, g_ENT);

    // prep
    round_tf32_kernel<<<(unsigned)((size_t)T_*D_/4/256), 256>>>(x, x32, (size_t)T_*D_/4);
    transpose_tf32_kernel<<<dim3(R_/32, D_/32, NC_), dim3(32, 8)>>>(cn, cnt32, D_, R_);
    transpose_tf32_kernel<<<dim3(D_/32, R_/32, NE_), dim3(32, 8)>>>(en, ent, R_, D_);
    router3_kernel<<<T_, 256>>>(x, wq, wk, wv);
    // main pipeline
    compress_mma_kernel<<<dim3(R_/64, T_/128), 256, ESMEM_TOTAL>>>();
    attn_tc_kernel<<<dim3(S_/128, B_*H_), 256, ATT_SMEM>>>();
    router_o_kernel<<<T_, 256>>>(wo);
    expand_mma_kernel<<<dim3(D_/64, T_/128), 256, ESMEM_TOTAL>>>(out);
}